// round 8
// baseline (speedup 1.0000x reference)
#include <cuda_runtime.h>
#include <cuda_bf16.h>
#include <cstdint>

#define LQ 2048
#define BB 8
#define DD 768
#define MROWS (BB * LQ)
#define ZB (2 * BB)                 // branch*8 + batch
#define QKSCALE 0.0360843918243516f

using bf16 = __nv_bfloat16;

// ---------------------------------------------------------------------------
// Scratch (device globals; allocation-free per harness rules)
// ---------------------------------------------------------------------------
__device__ __align__(16) float g_S[(size_t)ZB * LQ * LQ];     // 256MB logits, both branches
__device__ __align__(16) bf16  g_Phi[(size_t)ZB * LQ * LQ];   // 128MB
__device__ __align__(16) bf16  g_Plo[(size_t)ZB * LQ * LQ];   // 128MB
__device__ __align__(16) bf16  g_qhi[(size_t)MROWS * DD], g_qlo[(size_t)MROWS * DD];
__device__ __align__(16) bf16  g_kvhi[(size_t)2 * MROWS * DD], g_kvlo[(size_t)2 * MROWS * DD];
__device__ __align__(16) bf16  g_kThi[(size_t)2 * MROWS * DD], g_kTlo[(size_t)2 * MROWS * DD];
__device__ __align__(16) bf16  g_chi[(size_t)2 * MROWS * DD], g_clo[(size_t)2 * MROWS * DD];
__device__ __align__(16) bf16  g_Whi[2 * DD * DD], g_Wlo[2 * DD * DD];
__device__ __align__(16) float g_y[(size_t)2 * MROWS * DD];   // conv out, both branches
__device__ float g_part[2 * 2 * 128 * DD];
__device__ float g_stats[2 * 2 * DD];

// ---------------------------------------------------------------------------
// Helpers (baseline PTX only: ldmatrix / mma.sync / cp.async)
// ---------------------------------------------------------------------------
__device__ __forceinline__ uint32_t smem_u32(const void* p) {
    uint32_t a;
    asm("{ .reg .u64 t; cvta.to.shared.u64 t, %1; cvt.u32.u64 %0, t; }" : "=r"(a) : "l"(p));
    return a;
}
__device__ __forceinline__ void cp16(uint32_t saddr, const void* gaddr) {
    asm volatile("cp.async.cg.shared.global [%0], [%1], 16;" :: "r"(saddr), "l"(gaddr));
}
#define CP_COMMIT() asm volatile("cp.async.commit_group;" ::: "memory")
#define CP_WAIT0()  asm volatile("cp.async.wait_group 0;" ::: "memory")
#define CP_WAIT1()  asm volatile("cp.async.wait_group 1;" ::: "memory")

__device__ __forceinline__ void ldmat_x4(uint32_t& r0, uint32_t& r1, uint32_t& r2,
                                         uint32_t& r3, uint32_t addr) {
    asm volatile("ldmatrix.sync.aligned.m8n8.x4.shared.b16 {%0,%1,%2,%3}, [%4];"
                 : "=r"(r0), "=r"(r1), "=r"(r2), "=r"(r3) : "r"(addr));
}
__device__ __forceinline__ void mma16816(float* c, uint32_t a0, uint32_t a1,
                                         uint32_t a2, uint32_t a3,
                                         uint32_t b0, uint32_t b1) {
    asm volatile(
        "mma.sync.aligned.m16n8k16.row.col.f32.bf16.bf16.f32 "
        "{%0,%1,%2,%3}, {%4,%5,%6,%7}, {%8,%9}, {%0,%1,%2,%3};"
        : "+f"(c[0]), "+f"(c[1]), "+f"(c[2]), "+f"(c[3])
        : "r"(a0), "r"(a1), "r"(a2), "r"(a3), "r"(b0), "r"(b1));
}

__device__ __forceinline__ uint32_t sw_off(int row, int kbyte) {
    uint32_t off = (uint32_t)row * 128u + (uint32_t)kbyte;
    return off ^ ((off >> 3) & 0x70u);
}
__device__ __forceinline__ void split1(float v, uint16_t& h, uint16_t& l) {
    bf16 hb = __float2bfloat16(v);
    h = __bfloat16_as_ushort(hb);
    l = __bfloat16_as_ushort(__float2bfloat16(v - __bfloat162float(hb)));
}
__device__ __forceinline__ uint32_t pack_hi(float a, float b) {
    uint16_t ha, la, hb, lb; split1(a, ha, la); split1(b, hb, lb);
    return (uint32_t)ha | ((uint32_t)hb << 16);
}
__device__ __forceinline__ uint32_t pack_lo(float a, float b) {
    uint16_t ha, la, hb, lb; split1(a, ha, la); split1(b, hb, lb);
    return (uint32_t)la | ((uint32_t)lb << 16);
}

// ---------------------------------------------------------------------------
// Split-bf16 warp-MMA GEMM: C[m,n] = alpha * sum_k A[m,k]*B[n,k]
// 128x128 CTA tile, 256 threads / 8 warps (2x4 grid, 64x32 warp tiles),
// K in 64-chunks, 3-stage cp.async pipeline.
// PRODUCT-MAJOR MMA ordering: per ks, three sweeps (hh, hl, lh) over all 16
// accumulators, so same-acc MMAs are 16 apart (no RAW accumulator chains).
// A batch index = z & amask; B/C batch index = z.
// OUTMODE 0: fp32 C.  OUTMODE 1: split-bf16 C (Chi/Clo).
// ---------------------------------------------------------------------------
#define STAGE_BYTES 65536
#define GEMM_SMEM (3 * STAGE_BYTES)
#define GTHREADS 256

__device__ __forceinline__ void stage_load(uint32_t sdst, const bf16* __restrict__ Ahi,
                                           const bf16* __restrict__ Alo,
                                           const bf16* __restrict__ Bhi,
                                           const bf16* __restrict__ Blo,
                                           int K, int k0, int t) {
#pragma unroll
    for (int i = 0; i < 4; i++) {
        int idx = t + i * GTHREADS;       // 0..1023
        int row = idx >> 3, ch = idx & 7; // 16B chunk in 128B row
        uint32_t so = sw_off(row, ch * 16);
        size_t go = (size_t)row * K + k0 + ch * 8;
        cp16(sdst + so,         Ahi + go);
        cp16(sdst + 16384 + so, Alo + go);
        cp16(sdst + 32768 + so, Bhi + go);
        cp16(sdst + 49152 + so, Blo + go);
    }
}

template<int OUTMODE>
__global__ void __launch_bounds__(GTHREADS, 1)
mma_gemm(const bf16* __restrict__ Ahi, const bf16* __restrict__ Alo,
         const bf16* __restrict__ Bhi, const bf16* __restrict__ Blo,
         float* __restrict__ C, bf16* __restrict__ Chi, bf16* __restrict__ Clo,
         int K, int ldc, long sA, long sB, long sC, float alpha, int amask)
{
    extern __shared__ __align__(1024) char smem[];
    const uint32_t sb = smem_u32(smem);
    const int t = threadIdx.x, lane = t & 31, wid = t >> 5;
    const int wm = wid & 1, wn = wid >> 1;          // 2x4 warp grid, 64x32 tiles
    const int m0 = blockIdx.y * 128, n0 = blockIdx.x * 128, z = blockIdx.z;
    const int kiters = K >> 6;

    Ahi += (size_t)(z & amask) * sA + (size_t)m0 * K;
    Alo += (size_t)(z & amask) * sA + (size_t)m0 * K;
    Bhi += (size_t)z * sB + (size_t)n0 * K;
    Blo += (size_t)z * sB + (size_t)n0 * K;

    float acc[4][4][4];
#pragma unroll
    for (int i = 0; i < 4; i++)
#pragma unroll
        for (int j = 0; j < 4; j++)
#pragma unroll
            for (int q = 0; q < 4; q++) acc[i][j][q] = 0.f;

    // ldmatrix lane-address components
    const int a_m_add = (lane & 7) + ((lane >> 3) & 1) * 8;
    const int a_k_add = ((lane >> 4) & 1) * 8;
    // B x4: matrices (0,1) = n-tile +0 @ k 0/8; matrices (2,3) = n-tile +8 @ k 0/8
    const int b_n_add = (lane & 7) + ((lane >> 4) << 3);
    const int b_k_add = ((lane >> 3) & 1) * 8;

    stage_load(sb, Ahi, Alo, Bhi, Blo, K, 0, t);
    CP_COMMIT();
    if (kiters > 1) {
        stage_load(sb + STAGE_BYTES, Ahi, Alo, Bhi, Blo, K, 64, t);
        CP_COMMIT();
    }

    uint32_t cur = 0;  // rotating stage index
    for (int it = 0; it < kiters; it++) {
        if (it + 1 < kiters) { CP_WAIT1(); } else { CP_WAIT0(); }
        __syncthreads();
        if (it + 2 < kiters) {
            uint32_t nxt = cur + 2; if (nxt >= 3) nxt -= 3;
            stage_load(sb + nxt * STAGE_BYTES, Ahi, Alo, Bhi, Blo, K, (it + 2) << 6, t);
            CP_COMMIT();
        }
        const uint32_t st = sb + cur * STAGE_BYTES;

#pragma unroll
        for (int ks = 0; ks < 4; ks++) {
            const int kb = ks * 16;
            uint32_t ah[4][4], al[4][4];
#pragma unroll
            for (int tm = 0; tm < 4; tm++) {
                int m = wm * 64 + tm * 16 + a_m_add;
                uint32_t so = sw_off(m, (kb + a_k_add) * 2);
                ldmat_x4(ah[tm][0], ah[tm][1], ah[tm][2], ah[tm][3], st + so);
                ldmat_x4(al[tm][0], al[tm][1], al[tm][2], al[tm][3], st + 16384 + so);
            }
            uint32_t bh[4][2], bl[4][2];
#pragma unroll
            for (int tn2 = 0; tn2 < 2; tn2++) {
                int n = wn * 32 + tn2 * 16 + b_n_add;
                uint32_t so = sw_off(n, (kb + b_k_add) * 2);
                ldmat_x4(bh[tn2 * 2][0], bh[tn2 * 2][1],
                         bh[tn2 * 2 + 1][0], bh[tn2 * 2 + 1][1], st + 32768 + so);
                ldmat_x4(bl[tn2 * 2][0], bl[tn2 * 2][1],
                         bl[tn2 * 2 + 1][0], bl[tn2 * 2 + 1][1], st + 49152 + so);
            }
            // ---- Product-major sweeps: no adjacent same-acc MMAs ----
#pragma unroll
            for (int tm = 0; tm < 4; tm++)
#pragma unroll
                for (int tn = 0; tn < 4; tn++)
                    mma16816(acc[tm][tn], ah[tm][0], ah[tm][1], ah[tm][2], ah[tm][3],
                             bh[tn][0], bh[tn][1]);
#pragma unroll
            for (int tm = 0; tm < 4; tm++)
#pragma unroll
                for (int tn = 0; tn < 4; tn++)
                    mma16816(acc[tm][tn], ah[tm][0], ah[tm][1], ah[tm][2], ah[tm][3],
                             bl[tn][0], bl[tn][1]);
#pragma unroll
            for (int tm = 0; tm < 4; tm++)
#pragma unroll
                for (int tn = 0; tn < 4; tn++)
                    mma16816(acc[tm][tn], al[tm][0], al[tm][1], al[tm][2], al[tm][3],
                             bh[tn][0], bh[tn][1]);
        }
        cur = cur + 1; if (cur >= 3) cur -= 3;
    }

    // Epilogue
    const int gid = lane >> 2, tig = lane & 3;
#pragma unroll
    for (int tm = 0; tm < 4; tm++) {
        const int r0 = m0 + wm * 64 + tm * 16 + gid;
#pragma unroll
        for (int tn = 0; tn < 4; tn++) {
            const int cN = n0 + wn * 32 + tn * 8 + tig * 2;
            float* a = acc[tm][tn];
            if (OUTMODE == 0) {
                *(float2*)(C + (size_t)z * sC + (size_t)r0 * ldc + cN) =
                    make_float2(a[0] * alpha, a[1] * alpha);
                *(float2*)(C + (size_t)z * sC + (size_t)(r0 + 8) * ldc + cN) =
                    make_float2(a[2] * alpha, a[3] * alpha);
            } else {
                *(uint32_t*)(Chi + (size_t)z * sC + (size_t)r0 * ldc + cN) = pack_hi(a[0], a[1]);
                *(uint32_t*)(Clo + (size_t)z * sC + (size_t)r0 * ldc + cN) = pack_lo(a[0], a[1]);
                *(uint32_t*)(Chi + (size_t)z * sC + (size_t)(r0 + 8) * ldc + cN) = pack_hi(a[2], a[3]);
                *(uint32_t*)(Clo + (size_t)z * sC + (size_t)(r0 + 8) * ldc + cN) = pack_lo(a[2], a[3]);
            }
        }
    }
}

// ---------------------------------------------------------------------------
// Prep kernels
// ---------------------------------------------------------------------------
// x [L,B,D] -> q split [B,L,D]
__global__ void split_q(const float* __restrict__ in, bf16* __restrict__ hi,
                        bf16* __restrict__ lo)
{
    const int l = blockIdx.x, b = blockIdx.y, t = threadIdx.x;
    const float* s = in + (size_t)l * (BB * DD) + (size_t)b * DD;
    const size_t o = ((size_t)b * LQ + l) * DD;
#pragma unroll
    for (int j = 0; j < 3; j++) {
        float v = s[t + j * 256];
        bf16 h = __float2bfloat16(v);
        hi[o + t + j * 256] = h;
        lo[o + t + j * 256] = __float2bfloat16(v - __bfloat162float(h));
    }
}

// W_a/W_v -> split (both branches, z picks source)
__global__ void split_w(const float* __restrict__ wa, const float* __restrict__ wv,
                        bf16* __restrict__ hi, bf16* __restrict__ lo)
{
    const int br = blockIdx.y;
    const int i = blockIdx.x * 256 + threadIdx.x;
    float v = (br ? wv : wa)[i];
    bf16 h = __float2bfloat16(v);
    hi[br * DD * DD + i] = h;
    lo[br * DD * DD + i] = __float2bfloat16(v - __bfloat162float(h));
}

// x_a/x_v [L,B,D] -> kv split [z][L][D] AND kvT split [z][D][L], z = br*8+b
__global__ void prep_kv(const float* __restrict__ xa, const float* __restrict__ xv,
                        bf16* __restrict__ kvhi, bf16* __restrict__ kvlo,
                        bf16* __restrict__ thi, bf16* __restrict__ tlo)
{
    __shared__ uint16_t th[32][33], tl[32][33];
    const int z = blockIdx.z, b = z & 7;
    const float* src = (z >> 3) ? xv : xa;
    const int d0 = blockIdx.x * 32, l0 = blockIdx.y * 32;
    const int tx = threadIdx.x, ty = threadIdx.y;
#pragma unroll
    for (int r = 0; r < 4; r++) {
        int l = l0 + ty + r * 8;
        float v = src[(size_t)l * (BB * DD) + (size_t)b * DD + d0 + tx];
        uint16_t h, lw; split1(v, h, lw);
        size_t o = ((size_t)z * LQ + l) * DD + d0 + tx;
        kvhi[o] = __ushort_as_bfloat16(h);
        kvlo[o] = __ushort_as_bfloat16(lw);
        th[ty + r * 8][tx] = h;
        tl[ty + r * 8][tx] = lw;
    }
    __syncthreads();
#pragma unroll
    for (int r = 0; r < 4; r++) {
        int d = d0 + ty + r * 8;
        size_t o = ((size_t)z * DD + d) * LQ + l0 + tx;
        thi[o] = __ushort_as_bfloat16(th[tx][ty + r * 8]);
        tlo[o] = __ushort_as_bfloat16(tl[tx][ty + r * 8]);
    }
}

// ---------------------------------------------------------------------------
// Softmax over 2048-wide rows -> split bf16. grid = ZB*LQ, block = 256.
// ---------------------------------------------------------------------------
__global__ void softmax_split(const float* __restrict__ S, bf16* __restrict__ Ph,
                              bf16* __restrict__ Pl)
{
    __shared__ float red[8];
    const float* p = S + (size_t)blockIdx.x * 2048;
    const int t = threadIdx.x;

    float4 v0 = ((const float4*)p)[t];
    float4 v1 = ((const float4*)p)[t + 256];

    float m = fmaxf(fmaxf(fmaxf(v0.x, v0.y), fmaxf(v0.z, v0.w)),
                    fmaxf(fmaxf(v1.x, v1.y), fmaxf(v1.z, v1.w)));
#pragma unroll
    for (int o = 16; o; o >>= 1) m = fmaxf(m, __shfl_xor_sync(~0u, m, o));
    if ((t & 31) == 0) red[t >> 5] = m;
    __syncthreads();
    float mx = red[0];
#pragma unroll
    for (int w = 1; w < 8; w++) mx = fmaxf(mx, red[w]);
    __syncthreads();

    v0.x = __expf(v0.x - mx); v0.y = __expf(v0.y - mx);
    v0.z = __expf(v0.z - mx); v0.w = __expf(v0.w - mx);
    v1.x = __expf(v1.x - mx); v1.y = __expf(v1.y - mx);
    v1.z = __expf(v1.z - mx); v1.w = __expf(v1.w - mx);

    float s = v0.x + v0.y + v0.z + v0.w + v1.x + v1.y + v1.z + v1.w;
#pragma unroll
    for (int o = 16; o; o >>= 1) s += __shfl_xor_sync(~0u, s, o);
    if ((t & 31) == 0) red[t >> 5] = s;
    __syncthreads();
    float sm = 0.f;
#pragma unroll
    for (int w = 0; w < 8; w++) sm += red[w];
    const float inv = 1.f / sm;

    v0.x *= inv; v0.y *= inv; v0.z *= inv; v0.w *= inv;
    v1.x *= inv; v1.y *= inv; v1.z *= inv; v1.w *= inv;

    const size_t base = (size_t)blockIdx.x * 2048;
    ((uint2*)(Ph + base))[t] = make_uint2(pack_hi(v0.x, v0.y), pack_hi(v0.z, v0.w));
    ((uint2*)(Pl + base))[t] = make_uint2(pack_lo(v0.x, v0.y), pack_lo(v0.z, v0.w));
    ((uint2*)(Ph + base))[t + 256] = make_uint2(pack_hi(v1.x, v1.y), pack_hi(v1.z, v1.w));
    ((uint2*)(Pl + base))[t + 256] = make_uint2(pack_lo(v1.x, v1.y), pack_lo(v1.z, v1.w));
}

// ---------------------------------------------------------------------------
// BatchNorm stats (two-stage, deterministic; grid.y = branch)
// ---------------------------------------------------------------------------
__global__ void bn_partial(const float* __restrict__ yAll, float* __restrict__ partAll)
{
    const int br = blockIdx.y, t = threadIdx.x;
    const float* base = yAll + (size_t)br * MROWS * DD + (size_t)blockIdx.x * 128 * DD;
    float* part = partAll + (size_t)br * 2 * 128 * DD;
    float s[3] = {0.f, 0.f, 0.f}, q[3] = {0.f, 0.f, 0.f};
    for (int r = 0; r < 128; r++) {
        const float* row = base + (size_t)r * DD;
#pragma unroll
        for (int j = 0; j < 3; j++) {
            float v = row[t + j * 256];
            s[j] += v; q[j] += v * v;
        }
    }
#pragma unroll
    for (int j = 0; j < 3; j++) {
        part[blockIdx.x * DD + t + j * 256] = s[j];
        part[128 * DD + blockIdx.x * DD + t + j * 256] = q[j];
    }
}

__global__ void bn_finalize(const float* __restrict__ partAll,
                            const float* __restrict__ ga, const float* __restrict__ ba,
                            const float* __restrict__ gv, const float* __restrict__ bv,
                            float* __restrict__ statsAll)
{
    const int br = blockIdx.y;
    const int c = blockIdx.x * 256 + threadIdx.x;
    const float* part = partAll + (size_t)br * 2 * 128 * DD;
    const float* gamma = br ? gv : ga;
    const float* beta  = br ? bv : ba;
    float* statsOut = statsAll + br * 2 * DD;
    float s = 0.f, q = 0.f;
    for (int k = 0; k < 128; k++) {
        s += part[k * DD + c];
        q += part[128 * DD + k * DD + c];
    }
    const float mean = s * (1.f / (float)MROWS);
    const float var  = q * (1.f / (float)MROWS) - mean * mean;
    const float scale = gamma[c] * rsqrtf(var + 1e-5f);
    statsOut[c]      = scale;
    statsOut[DD + c] = beta[c] - mean * scale;
}

// ---------------------------------------------------------------------------
// Combine: BN-apply + PReLU + residual + LayerNorm. grid = MROWS.
// ---------------------------------------------------------------------------
__global__ void combine_ln(const float* __restrict__ x,
                           const float* __restrict__ yAll,
                           const float* __restrict__ stats,
                           const float* __restrict__ pa,
                           const float* __restrict__ pv,
                           const float* __restrict__ lng,
                           const float* __restrict__ lnb,
                           float* __restrict__ out)
{
    __shared__ float rs[8], rq[8];
    const int pos = blockIdx.x;
    const int b = pos >> 11, l = pos & 2047;
    const size_t yoff = (size_t)pos * DD;
    const size_t xoff = (size_t)l * (BB * DD) + (size_t)b * DD;
    const int t = threadIdx.x;
    const float aa = pa[0], av = pv[0];
    const float* ya = yAll;
    const float* yv = yAll + (size_t)MROWS * DD;

    float vv[3];
    float s = 0.f, q = 0.f;
#pragma unroll
    for (int j = 0; j < 3; j++) {
        const int d = t + j * 256;
        float va = ya[yoff + d] * stats[d] + stats[DD + d];
        va = va > 0.f ? va : aa * va;
        float vb = yv[yoff + d] * stats[2 * DD + d] + stats[3 * DD + d];
        vb = vb > 0.f ? vb : av * vb;
        float val = x[xoff + d] + va + vb;
        vv[j] = val; s += val; q += val * val;
    }
#pragma unroll
    for (int o = 16; o; o >>= 1) {
        s += __shfl_xor_sync(~0u, s, o);
        q += __shfl_xor_sync(~0u, q, o);
    }
    if ((t & 31) == 0) { rs[t >> 5] = s; rq[t >> 5] = q; }
    __syncthreads();
    s = 0.f; q = 0.f;
#pragma unroll
    for (int w = 0; w < 8; w++) { s += rs[w]; q += rq[w]; }
    const float mean = s * (1.f / (float)DD);
    const float var  = q * (1.f / (float)DD) - mean * mean;
    const float rstd = rsqrtf(var + 1e-5f);
#pragma unroll
    for (int j = 0; j < 3; j++) {
        const int d = t + j * 256;
        out[xoff + d] = (vv[j] - mean) * rstd * lng[d] + lnb[d];
    }
}

// ---------------------------------------------------------------------------
// Host orchestration (graph-capturable)
// ---------------------------------------------------------------------------
extern "C" void kernel_launch(void* const* d_in, const int* in_sizes, int n_in,
                              void* d_out, int out_size)
{
    const float* x_a    = (const float*)d_in[0];
    const float* x_v    = (const float*)d_in[1];
    const float* x      = (const float*)d_in[2];
    const float* W_a    = (const float*)d_in[3];
    const float* bn_a_g = (const float*)d_in[5];
    const float* bn_a_b = (const float*)d_in[6];
    const float* pre_a  = (const float*)d_in[7];
    const float* W_v    = (const float*)d_in[8];
    const float* bn_v_g = (const float*)d_in[10];
    const float* bn_v_b = (const float*)d_in[11];
    const float* pre_v  = (const float*)d_in[12];
    const float* ln_g   = (const float*)d_in[13];
    const float* ln_b   = (const float*)d_in[14];
    float* out = (float*)d_out;

    float *S, *y, *part, *stats;
    bf16 *Phi, *Plo, *qhi, *qlo, *kvhi, *kvlo, *kThi, *kTlo, *chi, *clo, *Whi, *Wlo;
    cudaGetSymbolAddress((void**)&S,    g_S);
    cudaGetSymbolAddress((void**)&Phi,  g_Phi);
    cudaGetSymbolAddress((void**)&Plo,  g_Plo);
    cudaGetSymbolAddress((void**)&qhi,  g_qhi);
    cudaGetSymbolAddress((void**)&qlo,  g_qlo);
    cudaGetSymbolAddress((void**)&kvhi, g_kvhi);
    cudaGetSymbolAddress((void**)&kvlo, g_kvlo);
    cudaGetSymbolAddress((void**)&kThi, g_kThi);
    cudaGetSymbolAddress((void**)&kTlo, g_kTlo);
    cudaGetSymbolAddress((void**)&chi,  g_chi);
    cudaGetSymbolAddress((void**)&clo,  g_clo);
    cudaGetSymbolAddress((void**)&Whi,  g_Whi);
    cudaGetSymbolAddress((void**)&Wlo,  g_Wlo);
    cudaGetSymbolAddress((void**)&y,    g_y);
    cudaGetSymbolAddress((void**)&part, g_part);
    cudaGetSymbolAddress((void**)&stats, g_stats);

    cudaFuncSetAttribute(mma_gemm<0>, cudaFuncAttributeMaxDynamicSharedMemorySize, GEMM_SMEM);
    cudaFuncSetAttribute(mma_gemm<1>, cudaFuncAttributeMaxDynamicSharedMemorySize, GEMM_SMEM);

    // Prep: q, W, kv/kvT (both branches each)
    split_q<<<dim3(LQ, BB), 256>>>(x, qhi, qlo);
    split_w<<<dim3((DD * DD) / 256, 2), 256>>>(W_a, W_v, Whi, Wlo);
    prep_kv<<<dim3(DD / 32, LQ / 32, ZB), dim3(32, 8)>>>(x_a, x_v, kvhi, kvlo, kThi, kTlo);

    // GEMM1: S[z,i,j] = scale * q[z&7,i,:].kv[z,j,:]  (M=2048,N=2048,K=768, z=16)
    mma_gemm<0><<<dim3(16, 16, ZB), GTHREADS, GEMM_SMEM>>>(
        qhi, qlo, kvhi, kvlo, S, nullptr, nullptr,
        DD, LQ, (long)LQ * DD, (long)LQ * DD, (long)LQ * LQ, QKSCALE, 7);

    softmax_split<<<ZB * LQ, 256>>>(S, Phi, Plo);

    // GEMM2: ctx[z,i,d] = P[z,i,:].kvT[z,d,:]  (M=2048,N=768,K=2048, z=16)
    mma_gemm<1><<<dim3(6, 16, ZB), GTHREADS, GEMM_SMEM>>>(
        Phi, Plo, kThi, kTlo, nullptr, chi, clo,
        LQ, DD, (long)LQ * LQ, (long)DD * LQ, (long)LQ * DD, 1.f, 0xFF);

    // GEMM3: y[br,r,e] = ctx[br,r,:].W[br,e,:]  (M=16384,N=768,K=768, z=2)
    mma_gemm<0><<<dim3(6, 128, 2), GTHREADS, GEMM_SMEM>>>(
        chi, clo, Whi, Wlo, y, nullptr, nullptr,
        DD, DD, (long)MROWS * DD, (long)DD * DD, (long)MROWS * DD, 1.f, 0xFF);

    bn_partial<<<dim3(128, 2), 256>>>(y, part);
    bn_finalize<<<dim3(3, 2), 256>>>(part, bn_a_g, bn_a_b, bn_v_g, bn_v_b, stats);

    combine_ln<<<MROWS, 256>>>(x, y, stats, pre_a, pre_v, ln_g, ln_b, out);
}

// round 9
// speedup vs baseline: 1.3628x; 1.3628x over previous
#include <cuda_runtime.h>
#include <cuda_fp16.h>
#include <cstdint>

#define LQ 2048
#define BB 8
#define DD 768
#define MROWS (BB * LQ)
#define ZB (2 * BB)                 // branch*8 + batch
#define QKSCALE 0.0360843918243516f

using f16 = __half;

// ---------------------------------------------------------------------------
// Scratch (device globals; allocation-free per harness rules)
// ---------------------------------------------------------------------------
__device__ __align__(16) float g_S[(size_t)ZB * LQ * LQ];     // 256MB logits, both branches
__device__ __align__(16) f16   g_Phi[(size_t)ZB * LQ * LQ];   // softmax hi
__device__ __align__(16) f16   g_Plo[(size_t)ZB * LQ * LQ];   // softmax lo
__device__ __align__(16) f16   g_qhi[(size_t)MROWS * DD], g_qlo[(size_t)MROWS * DD];
__device__ __align__(16) f16   g_kvhi[(size_t)2 * MROWS * DD];    // B of GEMM1: hi only
__device__ __align__(16) f16   g_kThi[(size_t)2 * MROWS * DD];    // B of GEMM2: hi only
__device__ __align__(16) f16   g_chi[(size_t)2 * MROWS * DD], g_clo[(size_t)2 * MROWS * DD];
__device__ __align__(16) f16   g_Whi[2 * DD * DD];                // B of GEMM3: hi only
__device__ __align__(16) float g_y[(size_t)2 * MROWS * DD];   // conv out, both branches
__device__ float g_part[2 * 2 * 128 * DD];
__device__ float g_stats[2 * 2 * DD];

// ---------------------------------------------------------------------------
// Helpers (baseline PTX only: ldmatrix / mma.sync / cp.async)
// ---------------------------------------------------------------------------
__device__ __forceinline__ uint32_t smem_u32(const void* p) {
    uint32_t a;
    asm("{ .reg .u64 t; cvta.to.shared.u64 t, %1; cvt.u32.u64 %0, t; }" : "=r"(a) : "l"(p));
    return a;
}
__device__ __forceinline__ void cp16(uint32_t saddr, const void* gaddr) {
    asm volatile("cp.async.cg.shared.global [%0], [%1], 16;" :: "r"(saddr), "l"(gaddr));
}
#define CP_COMMIT() asm volatile("cp.async.commit_group;" ::: "memory")
#define CP_WAIT0()  asm volatile("cp.async.wait_group 0;" ::: "memory")
#define CP_WAIT1()  asm volatile("cp.async.wait_group 1;" ::: "memory")

__device__ __forceinline__ void ldmat_x4(uint32_t& r0, uint32_t& r1, uint32_t& r2,
                                         uint32_t& r3, uint32_t addr) {
    asm volatile("ldmatrix.sync.aligned.m8n8.x4.shared.b16 {%0,%1,%2,%3}, [%4];"
                 : "=r"(r0), "=r"(r1), "=r"(r2), "=r"(r3) : "r"(addr));
}
__device__ __forceinline__ void mma16816(float* c, uint32_t a0, uint32_t a1,
                                         uint32_t a2, uint32_t a3,
                                         uint32_t b0, uint32_t b1) {
    asm volatile(
        "mma.sync.aligned.m16n8k16.row.col.f32.f16.f16.f32 "
        "{%0,%1,%2,%3}, {%4,%5,%6,%7}, {%8,%9}, {%0,%1,%2,%3};"
        : "+f"(c[0]), "+f"(c[1]), "+f"(c[2]), "+f"(c[3])
        : "r"(a0), "r"(a1), "r"(a2), "r"(a3), "r"(b0), "r"(b1));
}

__device__ __forceinline__ uint32_t sw_off(int row, int kbyte) {
    uint32_t off = (uint32_t)row * 128u + (uint32_t)kbyte;
    return off ^ ((off >> 3) & 0x70u);
}
__device__ __forceinline__ void split1(float v, uint16_t& h, uint16_t& l) {
    f16 hb = __float2half(v);
    h = __half_as_ushort(hb);
    l = __half_as_ushort(__float2half(v - __half2float(hb)));
}
__device__ __forceinline__ uint32_t pack_hi(float a, float b) {
    uint16_t ha, la, hb, lb; split1(a, ha, la); split1(b, hb, lb);
    return (uint32_t)ha | ((uint32_t)hb << 16);
}
__device__ __forceinline__ uint32_t pack_lo(float a, float b) {
    uint16_t ha, la, hb, lb; split1(a, ha, la); split1(b, hb, lb);
    return (uint32_t)la | ((uint32_t)lb << 16);
}

// ---------------------------------------------------------------------------
// Split-fp16 warp-MMA GEMM: C[m,n] = alpha * sum_k A[m,k]*B[n,k]
// A = A_hi + A_lo (fp16 split); B = B_hi (single fp16) -> 2 MMAs per tile:
//   C += A_hi*B_hi + A_lo*B_hi = A*B_hi  (dropped A*B_lo ~ 2^-12 relative)
// 128x128 CTA tile, 256 threads / 8 warps (2x4 grid, 64x32 warp tiles),
// K in 64-chunks, 3-stage cp.async pipeline (48KB/stage).
// A batch index = z & amask; B/C batch index = z.
// OUTMODE 0: fp32 C.  OUTMODE 1: split-fp16 C (Chi/Clo).
// ---------------------------------------------------------------------------
#define STAGE_BYTES 49152
#define GEMM_SMEM (3 * STAGE_BYTES)
#define GTHREADS 256

__device__ __forceinline__ void stage_load(uint32_t sdst, const f16* __restrict__ Ahi,
                                           const f16* __restrict__ Alo,
                                           const f16* __restrict__ Bhi,
                                           int K, int k0, int t) {
#pragma unroll
    for (int i = 0; i < 4; i++) {
        int idx = t + i * GTHREADS;       // 0..1023
        int row = idx >> 3, ch = idx & 7; // 16B chunk in 128B row
        uint32_t so = sw_off(row, ch * 16);
        size_t go = (size_t)row * K + k0 + ch * 8;
        cp16(sdst + so,         Ahi + go);
        cp16(sdst + 16384 + so, Alo + go);
        cp16(sdst + 32768 + so, Bhi + go);
    }
}

template<int OUTMODE>
__global__ void __launch_bounds__(GTHREADS, 1)
mma_gemm(const f16* __restrict__ Ahi, const f16* __restrict__ Alo,
         const f16* __restrict__ Bhi,
         float* __restrict__ C, f16* __restrict__ Chi, f16* __restrict__ Clo,
         int K, int ldc, long sA, long sB, long sC, float alpha, int amask)
{
    extern __shared__ __align__(1024) char smem[];
    const uint32_t sb = smem_u32(smem);
    const int t = threadIdx.x, lane = t & 31, wid = t >> 5;
    const int wm = wid & 1, wn = wid >> 1;          // 2x4 warp grid, 64x32 tiles
    const int m0 = blockIdx.y * 128, n0 = blockIdx.x * 128, z = blockIdx.z;
    const int kiters = K >> 6;

    Ahi += (size_t)(z & amask) * sA + (size_t)m0 * K;
    Alo += (size_t)(z & amask) * sA + (size_t)m0 * K;
    Bhi += (size_t)z * sB + (size_t)n0 * K;

    float acc[4][4][4];
#pragma unroll
    for (int i = 0; i < 4; i++)
#pragma unroll
        for (int j = 0; j < 4; j++)
#pragma unroll
            for (int q = 0; q < 4; q++) acc[i][j][q] = 0.f;

    // ldmatrix lane-address components
    const int a_m_add = (lane & 7) + ((lane >> 3) & 1) * 8;
    const int a_k_add = ((lane >> 4) & 1) * 8;
    // B x4: matrices (0,1) = n-tile +0 @ k 0/8; matrices (2,3) = n-tile +8 @ k 0/8
    const int b_n_add = (lane & 7) + ((lane >> 4) << 3);
    const int b_k_add = ((lane >> 3) & 1) * 8;

    stage_load(sb, Ahi, Alo, Bhi, K, 0, t);
    CP_COMMIT();
    if (kiters > 1) {
        stage_load(sb + STAGE_BYTES, Ahi, Alo, Bhi, K, 64, t);
        CP_COMMIT();
    }

    uint32_t cur = 0;  // rotating stage index
    for (int it = 0; it < kiters; it++) {
        if (it + 1 < kiters) { CP_WAIT1(); } else { CP_WAIT0(); }
        __syncthreads();
        if (it + 2 < kiters) {
            uint32_t nxt = cur + 2; if (nxt >= 3) nxt -= 3;
            stage_load(sb + nxt * STAGE_BYTES, Ahi, Alo, Bhi, K, (it + 2) << 6, t);
            CP_COMMIT();
        }
        const uint32_t st = sb + cur * STAGE_BYTES;

#pragma unroll
        for (int ks = 0; ks < 4; ks++) {
            const int kb = ks * 16;
            uint32_t ah[4][4], al[4][4];
#pragma unroll
            for (int tm = 0; tm < 4; tm++) {
                int m = wm * 64 + tm * 16 + a_m_add;
                uint32_t so = sw_off(m, (kb + a_k_add) * 2);
                ldmat_x4(ah[tm][0], ah[tm][1], ah[tm][2], ah[tm][3], st + so);
                ldmat_x4(al[tm][0], al[tm][1], al[tm][2], al[tm][3], st + 16384 + so);
            }
            uint32_t bh[4][2];
#pragma unroll
            for (int tn2 = 0; tn2 < 2; tn2++) {
                int n = wn * 32 + tn2 * 16 + b_n_add;
                uint32_t so = sw_off(n, (kb + b_k_add) * 2);
                ldmat_x4(bh[tn2 * 2][0], bh[tn2 * 2][1],
                         bh[tn2 * 2 + 1][0], bh[tn2 * 2 + 1][1], st + 32768 + so);
            }
#pragma unroll
            for (int tm = 0; tm < 4; tm++)
#pragma unroll
                for (int tn = 0; tn < 4; tn++) {
                    mma16816(acc[tm][tn], ah[tm][0], ah[tm][1], ah[tm][2], ah[tm][3],
                             bh[tn][0], bh[tn][1]);
                    mma16816(acc[tm][tn], al[tm][0], al[tm][1], al[tm][2], al[tm][3],
                             bh[tn][0], bh[tn][1]);
                }
        }
        cur = cur + 1; if (cur >= 3) cur -= 3;
    }

    // Epilogue
    const int gid = lane >> 2, tig = lane & 3;
#pragma unroll
    for (int tm = 0; tm < 4; tm++) {
        const int r0 = m0 + wm * 64 + tm * 16 + gid;
#pragma unroll
        for (int tn = 0; tn < 4; tn++) {
            const int cN = n0 + wn * 32 + tn * 8 + tig * 2;
            float* a = acc[tm][tn];
            if (OUTMODE == 0) {
                *(float2*)(C + (size_t)z * sC + (size_t)r0 * ldc + cN) =
                    make_float2(a[0] * alpha, a[1] * alpha);
                *(float2*)(C + (size_t)z * sC + (size_t)(r0 + 8) * ldc + cN) =
                    make_float2(a[2] * alpha, a[3] * alpha);
            } else {
                *(uint32_t*)(Chi + (size_t)z * sC + (size_t)r0 * ldc + cN) = pack_hi(a[0], a[1]);
                *(uint32_t*)(Clo + (size_t)z * sC + (size_t)r0 * ldc + cN) = pack_lo(a[0], a[1]);
                *(uint32_t*)(Chi + (size_t)z * sC + (size_t)(r0 + 8) * ldc + cN) = pack_hi(a[2], a[3]);
                *(uint32_t*)(Clo + (size_t)z * sC + (size_t)(r0 + 8) * ldc + cN) = pack_lo(a[2], a[3]);
            }
        }
    }
}

// ---------------------------------------------------------------------------
// Prep kernels
// ---------------------------------------------------------------------------
// x [L,B,D] -> q split [B,L,D] (A operand: hi+lo)
__global__ void split_q(const float* __restrict__ in, f16* __restrict__ hi,
                        f16* __restrict__ lo)
{
    const int l = blockIdx.x, b = blockIdx.y, t = threadIdx.x;
    const float* s = in + (size_t)l * (BB * DD) + (size_t)b * DD;
    const size_t o = ((size_t)b * LQ + l) * DD;
#pragma unroll
    for (int j = 0; j < 3; j++) {
        float v = s[t + j * 256];
        f16 h = __float2half(v);
        hi[o + t + j * 256] = h;
        lo[o + t + j * 256] = __float2half(v - __half2float(h));
    }
}

// W_a/W_v -> fp16 hi only (B operand of GEMM3)
__global__ void convert_w(const float* __restrict__ wa, const float* __restrict__ wv,
                          f16* __restrict__ hi)
{
    const int br = blockIdx.y;
    const int i = blockIdx.x * 256 + threadIdx.x;
    hi[br * DD * DD + i] = __float2half((br ? wv : wa)[i]);
}

// x_a/x_v [L,B,D] -> kv hi [z][L][D] AND kvT hi [z][D][L], z = br*8+b
__global__ void prep_kv(const float* __restrict__ xa, const float* __restrict__ xv,
                        f16* __restrict__ kvhi, f16* __restrict__ thi)
{
    __shared__ uint16_t th[32][33];
    const int z = blockIdx.z, b = z & 7;
    const float* src = (z >> 3) ? xv : xa;
    const int d0 = blockIdx.x * 32, l0 = blockIdx.y * 32;
    const int tx = threadIdx.x, ty = threadIdx.y;
#pragma unroll
    for (int r = 0; r < 4; r++) {
        int l = l0 + ty + r * 8;
        float v = src[(size_t)l * (BB * DD) + (size_t)b * DD + d0 + tx];
        uint16_t h = __half_as_ushort(__float2half(v));
        kvhi[((size_t)z * LQ + l) * DD + d0 + tx] = __ushort_as_half(h);
        th[ty + r * 8][tx] = h;
    }
    __syncthreads();
#pragma unroll
    for (int r = 0; r < 4; r++) {
        int d = d0 + ty + r * 8;
        thi[((size_t)z * DD + d) * LQ + l0 + tx] = __ushort_as_half(th[tx][ty + r * 8]);
    }
}

// ---------------------------------------------------------------------------
// Softmax over 2048-wide rows -> split fp16 (A operand of GEMM2).
// ---------------------------------------------------------------------------
__global__ void softmax_split(const float* __restrict__ S, f16* __restrict__ Ph,
                              f16* __restrict__ Pl)
{
    __shared__ float red[8];
    const float* p = S + (size_t)blockIdx.x * 2048;
    const int t = threadIdx.x;

    float4 v0 = ((const float4*)p)[t];
    float4 v1 = ((const float4*)p)[t + 256];

    float m = fmaxf(fmaxf(fmaxf(v0.x, v0.y), fmaxf(v0.z, v0.w)),
                    fmaxf(fmaxf(v1.x, v1.y), fmaxf(v1.z, v1.w)));
#pragma unroll
    for (int o = 16; o; o >>= 1) m = fmaxf(m, __shfl_xor_sync(~0u, m, o));
    if ((t & 31) == 0) red[t >> 5] = m;
    __syncthreads();
    float mx = red[0];
#pragma unroll
    for (int w = 1; w < 8; w++) mx = fmaxf(mx, red[w]);
    __syncthreads();

    v0.x = __expf(v0.x - mx); v0.y = __expf(v0.y - mx);
    v0.z = __expf(v0.z - mx); v0.w = __expf(v0.w - mx);
    v1.x = __expf(v1.x - mx); v1.y = __expf(v1.y - mx);
    v1.z = __expf(v1.z - mx); v1.w = __expf(v1.w - mx);

    float s = v0.x + v0.y + v0.z + v0.w + v1.x + v1.y + v1.z + v1.w;
#pragma unroll
    for (int o = 16; o; o >>= 1) s += __shfl_xor_sync(~0u, s, o);
    if ((t & 31) == 0) red[t >> 5] = s;
    __syncthreads();
    float sm = 0.f;
#pragma unroll
    for (int w = 0; w < 8; w++) sm += red[w];
    const float inv = 1.f / sm;

    v0.x *= inv; v0.y *= inv; v0.z *= inv; v0.w *= inv;
    v1.x *= inv; v1.y *= inv; v1.z *= inv; v1.w *= inv;

    const size_t base = (size_t)blockIdx.x * 2048;
    ((uint2*)(Ph + base))[t] = make_uint2(pack_hi(v0.x, v0.y), pack_hi(v0.z, v0.w));
    ((uint2*)(Pl + base))[t] = make_uint2(pack_lo(v0.x, v0.y), pack_lo(v0.z, v0.w));
    ((uint2*)(Ph + base))[t + 256] = make_uint2(pack_hi(v1.x, v1.y), pack_hi(v1.z, v1.w));
    ((uint2*)(Pl + base))[t + 256] = make_uint2(pack_lo(v1.x, v1.y), pack_lo(v1.z, v1.w));
}

// ---------------------------------------------------------------------------
// BatchNorm stats (two-stage, deterministic; grid.y = branch)
// ---------------------------------------------------------------------------
__global__ void bn_partial(const float* __restrict__ yAll, float* __restrict__ partAll)
{
    const int br = blockIdx.y, t = threadIdx.x;
    const float* base = yAll + (size_t)br * MROWS * DD + (size_t)blockIdx.x * 128 * DD;
    float* part = partAll + (size_t)br * 2 * 128 * DD;
    float s[3] = {0.f, 0.f, 0.f}, q[3] = {0.f, 0.f, 0.f};
    for (int r = 0; r < 128; r++) {
        const float* row = base + (size_t)r * DD;
#pragma unroll
        for (int j = 0; j < 3; j++) {
            float v = row[t + j * 256];
            s[j] += v; q[j] += v * v;
        }
    }
#pragma unroll
    for (int j = 0; j < 3; j++) {
        part[blockIdx.x * DD + t + j * 256] = s[j];
        part[128 * DD + blockIdx.x * DD + t + j * 256] = q[j];
    }
}

__global__ void bn_finalize(const float* __restrict__ partAll,
                            const float* __restrict__ ga, const float* __restrict__ ba,
                            const float* __restrict__ gv, const float* __restrict__ bv,
                            float* __restrict__ statsAll)
{
    const int br = blockIdx.y;
    const int c = blockIdx.x * 256 + threadIdx.x;
    const float* part = partAll + (size_t)br * 2 * 128 * DD;
    const float* gamma = br ? gv : ga;
    const float* beta  = br ? bv : ba;
    float* statsOut = statsAll + br * 2 * DD;
    float s = 0.f, q = 0.f;
    for (int k = 0; k < 128; k++) {
        s += part[k * DD + c];
        q += part[128 * DD + k * DD + c];
    }
    const float mean = s * (1.f / (float)MROWS);
    const float var  = q * (1.f / (float)MROWS) - mean * mean;
    const float scale = gamma[c] * rsqrtf(var + 1e-5f);
    statsOut[c]      = scale;
    statsOut[DD + c] = beta[c] - mean * scale;
}

// ---------------------------------------------------------------------------
// Combine: BN-apply + PReLU + residual + LayerNorm. grid = MROWS.
// ---------------------------------------------------------------------------
__global__ void combine_ln(const float* __restrict__ x,
                           const float* __restrict__ yAll,
                           const float* __restrict__ stats,
                           const float* __restrict__ pa,
                           const float* __restrict__ pv,
                           const float* __restrict__ lng,
                           const float* __restrict__ lnb,
                           float* __restrict__ out)
{
    __shared__ float rs[8], rq[8];
    const int pos = blockIdx.x;
    const int b = pos >> 11, l = pos & 2047;
    const size_t yoff = (size_t)pos * DD;
    const size_t xoff = (size_t)l * (BB * DD) + (size_t)b * DD;
    const int t = threadIdx.x;
    const float aa = pa[0], av = pv[0];
    const float* ya = yAll;
    const float* yv = yAll + (size_t)MROWS * DD;

    float vv[3];
    float s = 0.f, q = 0.f;
#pragma unroll
    for (int j = 0; j < 3; j++) {
        const int d = t + j * 256;
        float va = ya[yoff + d] * stats[d] + stats[DD + d];
        va = va > 0.f ? va : aa * va;
        float vb = yv[yoff + d] * stats[2 * DD + d] + stats[3 * DD + d];
        vb = vb > 0.f ? vb : av * vb;
        float val = x[xoff + d] + va + vb;
        vv[j] = val; s += val; q += val * val;
    }
#pragma unroll
    for (int o = 16; o; o >>= 1) {
        s += __shfl_xor_sync(~0u, s, o);
        q += __shfl_xor_sync(~0u, q, o);
    }
    if ((t & 31) == 0) { rs[t >> 5] = s; rq[t >> 5] = q; }
    __syncthreads();
    s = 0.f; q = 0.f;
#pragma unroll
    for (int w = 0; w < 8; w++) { s += rs[w]; q += rq[w]; }
    const float mean = s * (1.f / (float)DD);
    const float var  = q * (1.f / (float)DD) - mean * mean;
    const float rstd = rsqrtf(var + 1e-5f);
#pragma unroll
    for (int j = 0; j < 3; j++) {
        const int d = t + j * 256;
        out[xoff + d] = (vv[j] - mean) * rstd * lng[d] + lnb[d];
    }
}

// ---------------------------------------------------------------------------
// Host orchestration (graph-capturable)
// ---------------------------------------------------------------------------
extern "C" void kernel_launch(void* const* d_in, const int* in_sizes, int n_in,
                              void* d_out, int out_size)
{
    const float* x_a    = (const float*)d_in[0];
    const float* x_v    = (const float*)d_in[1];
    const float* x      = (const float*)d_in[2];
    const float* W_a    = (const float*)d_in[3];
    const float* bn_a_g = (const float*)d_in[5];
    const float* bn_a_b = (const float*)d_in[6];
    const float* pre_a  = (const float*)d_in[7];
    const float* W_v    = (const float*)d_in[8];
    const float* bn_v_g = (const float*)d_in[10];
    const float* bn_v_b = (const float*)d_in[11];
    const float* pre_v  = (const float*)d_in[12];
    const float* ln_g   = (const float*)d_in[13];
    const float* ln_b   = (const float*)d_in[14];
    float* out = (float*)d_out;

    float *S, *y, *part, *stats;
    f16 *Phi, *Plo, *qhi, *qlo, *kvhi, *kThi, *chi, *clo, *Whi;
    cudaGetSymbolAddress((void**)&S,    g_S);
    cudaGetSymbolAddress((void**)&Phi,  g_Phi);
    cudaGetSymbolAddress((void**)&Plo,  g_Plo);
    cudaGetSymbolAddress((void**)&qhi,  g_qhi);
    cudaGetSymbolAddress((void**)&qlo,  g_qlo);
    cudaGetSymbolAddress((void**)&kvhi, g_kvhi);
    cudaGetSymbolAddress((void**)&kThi, g_kThi);
    cudaGetSymbolAddress((void**)&chi,  g_chi);
    cudaGetSymbolAddress((void**)&clo,  g_clo);
    cudaGetSymbolAddress((void**)&Whi,  g_Whi);
    cudaGetSymbolAddress((void**)&y,    g_y);
    cudaGetSymbolAddress((void**)&part, g_part);
    cudaGetSymbolAddress((void**)&stats, g_stats);

    cudaFuncSetAttribute(mma_gemm<0>, cudaFuncAttributeMaxDynamicSharedMemorySize, GEMM_SMEM);
    cudaFuncSetAttribute(mma_gemm<1>, cudaFuncAttributeMaxDynamicSharedMemorySize, GEMM_SMEM);

    // Prep: q split, W hi, kv/kvT hi (both branches)
    split_q<<<dim3(LQ, BB), 256>>>(x, qhi, qlo);
    convert_w<<<dim3((DD * DD) / 256, 2), 256>>>(W_a, W_v, Whi);
    prep_kv<<<dim3(DD / 32, LQ / 32, ZB), dim3(32, 8)>>>(x_a, x_v, kvhi, kThi);

    // GEMM1: S[z,i,j] = scale * q[z&7,i,:].kv[z,j,:]  (M=2048,N=2048,K=768, z=16)
    mma_gemm<0><<<dim3(16, 16, ZB), GTHREADS, GEMM_SMEM>>>(
        qhi, qlo, kvhi, S, nullptr, nullptr,
        DD, LQ, (long)LQ * DD, (long)LQ * DD, (long)LQ * LQ, QKSCALE, 7);

    softmax_split<<<ZB * LQ, 256>>>(S, Phi, Plo);

    // GEMM2: ctx[z,i,d] = P[z,i,:].kvT[z,d,:]  (M=2048,N=768,K=2048, z=16)
    mma_gemm<1><<<dim3(6, 16, ZB), GTHREADS, GEMM_SMEM>>>(
        Phi, Plo, kThi, nullptr, chi, clo,
        LQ, DD, (long)LQ * LQ, (long)DD * LQ, (long)LQ * DD, 1.f, 0xFF);

    // GEMM3: y[br,r,e] = ctx[br,r,:].W[br,e,:]  (M=16384,N=768,K=768, z=2)
    mma_gemm<0><<<dim3(6, 128, 2), GTHREADS, GEMM_SMEM>>>(
        chi, clo, Whi, y, nullptr, nullptr,
        DD, DD, (long)MROWS * DD, (long)DD * DD, (long)MROWS * DD, 1.f, 0xFF);

    bn_partial<<<dim3(128, 2), 256>>>(y, part);
    bn_finalize<<<dim3(3, 2), 256>>>(part, bn_a_g, bn_a_b, bn_v_g, bn_v_b, stats);

    combine_ln<<<MROWS, 256>>>(x, y, stats, pre_a, pre_v, ln_g, ln_b, out);
}

// round 10
// speedup vs baseline: 2.0795x; 1.5259x over previous
#include <cuda_runtime.h>
#include <cuda_fp16.h>
#include <cstdint>

#define LQ 2048
#define BB 8
#define DD 768
#define MROWS (BB * LQ)
#define ZB (2 * BB)                 // branch*8 + batch
#define QKSCALE 0.0360843918243516f

using f16 = __half;

// ---------------------------------------------------------------------------
// Scratch (device globals; allocation-free per harness rules)
// ---------------------------------------------------------------------------
__device__ __align__(16) float g_S[(size_t)ZB * LQ * LQ];     // 256MB logits, both branches
__device__ __align__(16) f16   g_P[(size_t)ZB * LQ * LQ];     // softmax probs (fp16)
__device__ __align__(16) f16   g_q[(size_t)MROWS * DD];
__device__ __align__(16) f16   g_kv[(size_t)2 * MROWS * DD];
__device__ __align__(16) f16   g_kT[(size_t)2 * MROWS * DD];
__device__ __align__(16) f16   g_c[(size_t)2 * MROWS * DD];
__device__ __align__(16) f16   g_W[2 * DD * DD];
__device__ __align__(16) float g_y[(size_t)2 * MROWS * DD];   // conv out, both branches
__device__ float g_part[2 * 2 * 128 * DD];
__device__ float g_stats[2 * 2 * DD];

// ---------------------------------------------------------------------------
// Helpers (baseline PTX only: ldmatrix / mma.sync / cp.async)
// ---------------------------------------------------------------------------
__device__ __forceinline__ uint32_t smem_u32(const void* p) {
    uint32_t a;
    asm("{ .reg .u64 t; cvta.to.shared.u64 t, %1; cvt.u32.u64 %0, t; }" : "=r"(a) : "l"(p));
    return a;
}
__device__ __forceinline__ void cp16(uint32_t saddr, const void* gaddr) {
    asm volatile("cp.async.cg.shared.global [%0], [%1], 16;" :: "r"(saddr), "l"(gaddr));
}
#define CP_COMMIT() asm volatile("cp.async.commit_group;" ::: "memory")
#define CP_WAIT0()  asm volatile("cp.async.wait_group 0;" ::: "memory")
#define CP_WAIT1()  asm volatile("cp.async.wait_group 1;" ::: "memory")

__device__ __forceinline__ void ldmat_x4(uint32_t& r0, uint32_t& r1, uint32_t& r2,
                                         uint32_t& r3, uint32_t addr) {
    asm volatile("ldmatrix.sync.aligned.m8n8.x4.shared.b16 {%0,%1,%2,%3}, [%4];"
                 : "=r"(r0), "=r"(r1), "=r"(r2), "=r"(r3) : "r"(addr));
}
__device__ __forceinline__ void mma16816(float* c, uint32_t a0, uint32_t a1,
                                         uint32_t a2, uint32_t a3,
                                         uint32_t b0, uint32_t b1) {
    asm volatile(
        "mma.sync.aligned.m16n8k16.row.col.f32.f16.f16.f32 "
        "{%0,%1,%2,%3}, {%4,%5,%6,%7}, {%8,%9}, {%0,%1,%2,%3};"
        : "+f"(c[0]), "+f"(c[1]), "+f"(c[2]), "+f"(c[3])
        : "r"(a0), "r"(a1), "r"(a2), "r"(a3), "r"(b0), "r"(b1));
}

__device__ __forceinline__ uint32_t sw_off(int row, int kbyte) {
    uint32_t off = (uint32_t)row * 128u + (uint32_t)kbyte;
    return off ^ ((off >> 3) & 0x70u);
}
__device__ __forceinline__ uint32_t pack_h(float a, float b) {
    uint16_t ha = __half_as_ushort(__float2half(a));
    uint16_t hb = __half_as_ushort(__float2half(b));
    return (uint32_t)ha | ((uint32_t)hb << 16);
}

// ---------------------------------------------------------------------------
// fp16 warp-MMA GEMM: C[m,n] = alpha * sum_k A[m,k]*B[n,k]
// Pure fp16 operands (single rounding each), fp32 accumulate.
// 128x128 CTA tile, 256 threads / 8 warps (2x4 grid, 64x32 warp tiles),
// K in 64-chunks, 3-stage cp.async pipeline (32KB/stage).
// A batch index = z & amask; B/C batch index = z.
// OUTMODE 0: fp32 C.  OUTMODE 1: fp16 C.
// ---------------------------------------------------------------------------
#define STAGE_BYTES 32768
#define GEMM_SMEM (3 * STAGE_BYTES)
#define GTHREADS 256

__device__ __forceinline__ void stage_load(uint32_t sdst, const f16* __restrict__ A,
                                           const f16* __restrict__ B,
                                           int K, int k0, int t) {
#pragma unroll
    for (int i = 0; i < 4; i++) {
        int idx = t + i * GTHREADS;       // 0..1023
        int row = idx >> 3, ch = idx & 7; // 16B chunk in 128B row
        uint32_t so = sw_off(row, ch * 16);
        size_t go = (size_t)row * K + k0 + ch * 8;
        cp16(sdst + so,         A + go);
        cp16(sdst + 16384 + so, B + go);
    }
}

template<int OUTMODE>
__global__ void __launch_bounds__(GTHREADS, 1)
mma_gemm(const f16* __restrict__ A, const f16* __restrict__ B,
         float* __restrict__ C, f16* __restrict__ Ch,
         int K, int ldc, long sA, long sB, long sC, float alpha, int amask)
{
    extern __shared__ __align__(1024) char smem[];
    const uint32_t sb = smem_u32(smem);
    const int t = threadIdx.x, lane = t & 31, wid = t >> 5;
    const int wm = wid & 1, wn = wid >> 1;          // 2x4 warp grid, 64x32 tiles
    const int m0 = blockIdx.y * 128, n0 = blockIdx.x * 128, z = blockIdx.z;
    const int kiters = K >> 6;

    A += (size_t)(z & amask) * sA + (size_t)m0 * K;
    B += (size_t)z * sB + (size_t)n0 * K;

    float acc[4][4][4];
#pragma unroll
    for (int i = 0; i < 4; i++)
#pragma unroll
        for (int j = 0; j < 4; j++)
#pragma unroll
            for (int q = 0; q < 4; q++) acc[i][j][q] = 0.f;

    // ldmatrix lane-address components
    const int a_m_add = (lane & 7) + ((lane >> 3) & 1) * 8;
    const int a_k_add = ((lane >> 4) & 1) * 8;
    // B x4: matrices (0,1) = n-tile +0 @ k 0/8; matrices (2,3) = n-tile +8 @ k 0/8
    const int b_n_add = (lane & 7) + ((lane >> 4) << 3);
    const int b_k_add = ((lane >> 3) & 1) * 8;

    stage_load(sb, A, B, K, 0, t);
    CP_COMMIT();
    if (kiters > 1) {
        stage_load(sb + STAGE_BYTES, A, B, K, 64, t);
        CP_COMMIT();
    }

    uint32_t cur = 0;  // rotating stage index
    for (int it = 0; it < kiters; it++) {
        if (it + 1 < kiters) { CP_WAIT1(); } else { CP_WAIT0(); }
        __syncthreads();
        if (it + 2 < kiters) {
            uint32_t nxt = cur + 2; if (nxt >= 3) nxt -= 3;
            stage_load(sb + nxt * STAGE_BYTES, A, B, K, (it + 2) << 6, t);
            CP_COMMIT();
        }
        const uint32_t st = sb + cur * STAGE_BYTES;

#pragma unroll
        for (int ks = 0; ks < 4; ks++) {
            const int kb = ks * 16;
            uint32_t ah[4][4];
#pragma unroll
            for (int tm = 0; tm < 4; tm++) {
                int m = wm * 64 + tm * 16 + a_m_add;
                uint32_t so = sw_off(m, (kb + a_k_add) * 2);
                ldmat_x4(ah[tm][0], ah[tm][1], ah[tm][2], ah[tm][3], st + so);
            }
            uint32_t bh[4][2];
#pragma unroll
            for (int tn2 = 0; tn2 < 2; tn2++) {
                int n = wn * 32 + tn2 * 16 + b_n_add;
                uint32_t so = sw_off(n, (kb + b_k_add) * 2);
                ldmat_x4(bh[tn2 * 2][0], bh[tn2 * 2][1],
                         bh[tn2 * 2 + 1][0], bh[tn2 * 2 + 1][1], st + 16384 + so);
            }
#pragma unroll
            for (int tm = 0; tm < 4; tm++)
#pragma unroll
                for (int tn = 0; tn < 4; tn++)
                    mma16816(acc[tm][tn], ah[tm][0], ah[tm][1], ah[tm][2], ah[tm][3],
                             bh[tn][0], bh[tn][1]);
        }
        cur = cur + 1; if (cur >= 3) cur -= 3;
    }

    // Epilogue
    const int gid = lane >> 2, tig = lane & 3;
#pragma unroll
    for (int tm = 0; tm < 4; tm++) {
        const int r0 = m0 + wm * 64 + tm * 16 + gid;
#pragma unroll
        for (int tn = 0; tn < 4; tn++) {
            const int cN = n0 + wn * 32 + tn * 8 + tig * 2;
            float* a = acc[tm][tn];
            if (OUTMODE == 0) {
                *(float2*)(C + (size_t)z * sC + (size_t)r0 * ldc + cN) =
                    make_float2(a[0] * alpha, a[1] * alpha);
                *(float2*)(C + (size_t)z * sC + (size_t)(r0 + 8) * ldc + cN) =
                    make_float2(a[2] * alpha, a[3] * alpha);
            } else {
                *(uint32_t*)(Ch + (size_t)z * sC + (size_t)r0 * ldc + cN) = pack_h(a[0], a[1]);
                *(uint32_t*)(Ch + (size_t)z * sC + (size_t)(r0 + 8) * ldc + cN) = pack_h(a[2], a[3]);
            }
        }
    }
}

// ---------------------------------------------------------------------------
// Prep kernels
// ---------------------------------------------------------------------------
// x [L,B,D] -> q fp16 [B,L,D]
__global__ void convert_q(const float* __restrict__ in, f16* __restrict__ q)
{
    const int l = blockIdx.x, b = blockIdx.y, t = threadIdx.x;
    const float* s = in + (size_t)l * (BB * DD) + (size_t)b * DD;
    const size_t o = ((size_t)b * LQ + l) * DD;
#pragma unroll
    for (int j = 0; j < 3; j++)
        q[o + t + j * 256] = __float2half(s[t + j * 256]);
}

// W_a/W_v -> fp16
__global__ void convert_w(const float* __restrict__ wa, const float* __restrict__ wv,
                          f16* __restrict__ w)
{
    const int br = blockIdx.y;
    const int i = blockIdx.x * 256 + threadIdx.x;
    w[br * DD * DD + i] = __float2half((br ? wv : wa)[i]);
}

// x_a/x_v [L,B,D] -> kv fp16 [z][L][D] AND kvT fp16 [z][D][L], z = br*8+b
__global__ void prep_kv(const float* __restrict__ xa, const float* __restrict__ xv,
                        f16* __restrict__ kv, f16* __restrict__ kT)
{
    __shared__ uint16_t th[32][33];
    const int z = blockIdx.z, b = z & 7;
    const float* src = (z >> 3) ? xv : xa;
    const int d0 = blockIdx.x * 32, l0 = blockIdx.y * 32;
    const int tx = threadIdx.x, ty = threadIdx.y;
#pragma unroll
    for (int r = 0; r < 4; r++) {
        int l = l0 + ty + r * 8;
        float v = src[(size_t)l * (BB * DD) + (size_t)b * DD + d0 + tx];
        uint16_t h = __half_as_ushort(__float2half(v));
        kv[((size_t)z * LQ + l) * DD + d0 + tx] = __ushort_as_half(h);
        th[ty + r * 8][tx] = h;
    }
    __syncthreads();
#pragma unroll
    for (int r = 0; r < 4; r++) {
        int d = d0 + ty + r * 8;
        kT[((size_t)z * DD + d) * LQ + l0 + tx] = __ushort_as_half(th[tx][ty + r * 8]);
    }
}

// ---------------------------------------------------------------------------
// Softmax over 2048-wide rows -> fp16 probs. grid = ZB*LQ, block = 256.
// ---------------------------------------------------------------------------
__global__ void softmax_f16(const float* __restrict__ S, f16* __restrict__ P)
{
    __shared__ float red[8];
    const float* p = S + (size_t)blockIdx.x * 2048;
    const int t = threadIdx.x;

    float4 v0 = ((const float4*)p)[t];
    float4 v1 = ((const float4*)p)[t + 256];

    float m = fmaxf(fmaxf(fmaxf(v0.x, v0.y), fmaxf(v0.z, v0.w)),
                    fmaxf(fmaxf(v1.x, v1.y), fmaxf(v1.z, v1.w)));
#pragma unroll
    for (int o = 16; o; o >>= 1) m = fmaxf(m, __shfl_xor_sync(~0u, m, o));
    if ((t & 31) == 0) red[t >> 5] = m;
    __syncthreads();
    float mx = red[0];
#pragma unroll
    for (int w = 1; w < 8; w++) mx = fmaxf(mx, red[w]);
    __syncthreads();

    v0.x = __expf(v0.x - mx); v0.y = __expf(v0.y - mx);
    v0.z = __expf(v0.z - mx); v0.w = __expf(v0.w - mx);
    v1.x = __expf(v1.x - mx); v1.y = __expf(v1.y - mx);
    v1.z = __expf(v1.z - mx); v1.w = __expf(v1.w - mx);

    float s = v0.x + v0.y + v0.z + v0.w + v1.x + v1.y + v1.z + v1.w;
#pragma unroll
    for (int o = 16; o; o >>= 1) s += __shfl_xor_sync(~0u, s, o);
    if ((t & 31) == 0) red[t >> 5] = s;
    __syncthreads();
    float sm = 0.f;
#pragma unroll
    for (int w = 0; w < 8; w++) sm += red[w];
    const float inv = 1.f / sm;

    v0.x *= inv; v0.y *= inv; v0.z *= inv; v0.w *= inv;
    v1.x *= inv; v1.y *= inv; v1.z *= inv; v1.w *= inv;

    const size_t base = (size_t)blockIdx.x * 2048;
    ((uint2*)(P + base))[t] = make_uint2(pack_h(v0.x, v0.y), pack_h(v0.z, v0.w));
    ((uint2*)(P + base))[t + 256] = make_uint2(pack_h(v1.x, v1.y), pack_h(v1.z, v1.w));
}

// ---------------------------------------------------------------------------
// BatchNorm stats (two-stage, deterministic; grid.y = branch)
// ---------------------------------------------------------------------------
__global__ void bn_partial(const float* __restrict__ yAll, float* __restrict__ partAll)
{
    const int br = blockIdx.y, t = threadIdx.x;
    const float* base = yAll + (size_t)br * MROWS * DD + (size_t)blockIdx.x * 128 * DD;
    float* part = partAll + (size_t)br * 2 * 128 * DD;
    float s[3] = {0.f, 0.f, 0.f}, q[3] = {0.f, 0.f, 0.f};
    for (int r = 0; r < 128; r++) {
        const float* row = base + (size_t)r * DD;
#pragma unroll
        for (int j = 0; j < 3; j++) {
            float v = row[t + j * 256];
            s[j] += v; q[j] += v * v;
        }
    }
#pragma unroll
    for (int j = 0; j < 3; j++) {
        part[blockIdx.x * DD + t + j * 256] = s[j];
        part[128 * DD + blockIdx.x * DD + t + j * 256] = q[j];
    }
}

__global__ void bn_finalize(const float* __restrict__ partAll,
                            const float* __restrict__ ga, const float* __restrict__ ba,
                            const float* __restrict__ gv, const float* __restrict__ bv,
                            float* __restrict__ statsAll)
{
    const int br = blockIdx.y;
    const int c = blockIdx.x * 256 + threadIdx.x;
    const float* part = partAll + (size_t)br * 2 * 128 * DD;
    const float* gamma = br ? gv : ga;
    const float* beta  = br ? bv : ba;
    float* statsOut = statsAll + br * 2 * DD;
    float s = 0.f, q = 0.f;
    for (int k = 0; k < 128; k++) {
        s += part[k * DD + c];
        q += part[128 * DD + k * DD + c];
    }
    const float mean = s * (1.f / (float)MROWS);
    const float var  = q * (1.f / (float)MROWS) - mean * mean;
    const float scale = gamma[c] * rsqrtf(var + 1e-5f);
    statsOut[c]      = scale;
    statsOut[DD + c] = beta[c] - mean * scale;
}

// ---------------------------------------------------------------------------
// Combine: BN-apply + PReLU + residual + LayerNorm. grid = MROWS.
// ---------------------------------------------------------------------------
__global__ void combine_ln(const float* __restrict__ x,
                           const float* __restrict__ yAll,
                           const float* __restrict__ stats,
                           const float* __restrict__ pa,
                           const float* __restrict__ pv,
                           const float* __restrict__ lng,
                           const float* __restrict__ lnb,
                           float* __restrict__ out)
{
    __shared__ float rs[8], rq[8];
    const int pos = blockIdx.x;
    const int b = pos >> 11, l = pos & 2047;
    const size_t yoff = (size_t)pos * DD;
    const size_t xoff = (size_t)l * (BB * DD) + (size_t)b * DD;
    const int t = threadIdx.x;
    const float aa = pa[0], av = pv[0];
    const float* ya = yAll;
    const float* yv = yAll + (size_t)MROWS * DD;

    float vv[3];
    float s = 0.f, q = 0.f;
#pragma unroll
    for (int j = 0; j < 3; j++) {
        const int d = t + j * 256;
        float va = ya[yoff + d] * stats[d] + stats[DD + d];
        va = va > 0.f ? va : aa * va;
        float vb = yv[yoff + d] * stats[2 * DD + d] + stats[3 * DD + d];
        vb = vb > 0.f ? vb : av * vb;
        float val = x[xoff + d] + va + vb;
        vv[j] = val; s += val; q += val * val;
    }
#pragma unroll
    for (int o = 16; o; o >>= 1) {
        s += __shfl_xor_sync(~0u, s, o);
        q += __shfl_xor_sync(~0u, q, o);
    }
    if ((t & 31) == 0) { rs[t >> 5] = s; rq[t >> 5] = q; }
    __syncthreads();
    s = 0.f; q = 0.f;
#pragma unroll
    for (int w = 0; w < 8; w++) { s += rs[w]; q += rq[w]; }
    const float mean = s * (1.f / (float)DD);
    const float var  = q * (1.f / (float)DD) - mean * mean;
    const float rstd = rsqrtf(var + 1e-5f);
#pragma unroll
    for (int j = 0; j < 3; j++) {
        const int d = t + j * 256;
        out[xoff + d] = (vv[j] - mean) * rstd * lng[d] + lnb[d];
    }
}

// ---------------------------------------------------------------------------
// Host orchestration (graph-capturable)
// ---------------------------------------------------------------------------
extern "C" void kernel_launch(void* const* d_in, const int* in_sizes, int n_in,
                              void* d_out, int out_size)
{
    const float* x_a    = (const float*)d_in[0];
    const float* x_v    = (const float*)d_in[1];
    const float* x      = (const float*)d_in[2];
    const float* W_a    = (const float*)d_in[3];
    const float* bn_a_g = (const float*)d_in[5];
    const float* bn_a_b = (const float*)d_in[6];
    const float* pre_a  = (const float*)d_in[7];
    const float* W_v    = (const float*)d_in[8];
    const float* bn_v_g = (const float*)d_in[10];
    const float* bn_v_b = (const float*)d_in[11];
    const float* pre_v  = (const float*)d_in[12];
    const float* ln_g   = (const float*)d_in[13];
    const float* ln_b   = (const float*)d_in[14];
    float* out = (float*)d_out;

    float *S, *y, *part, *stats;
    f16 *P, *q, *kv, *kT, *c, *W;
    cudaGetSymbolAddress((void**)&S,    g_S);
    cudaGetSymbolAddress((void**)&P,    g_P);
    cudaGetSymbolAddress((void**)&q,    g_q);
    cudaGetSymbolAddress((void**)&kv,   g_kv);
    cudaGetSymbolAddress((void**)&kT,   g_kT);
    cudaGetSymbolAddress((void**)&c,    g_c);
    cudaGetSymbolAddress((void**)&W,    g_W);
    cudaGetSymbolAddress((void**)&y,    g_y);
    cudaGetSymbolAddress((void**)&part, g_part);
    cudaGetSymbolAddress((void**)&stats, g_stats);

    cudaFuncSetAttribute(mma_gemm<0>, cudaFuncAttributeMaxDynamicSharedMemorySize, GEMM_SMEM);
    cudaFuncSetAttribute(mma_gemm<1>, cudaFuncAttributeMaxDynamicSharedMemorySize, GEMM_SMEM);

    // Prep: q, W, kv/kvT (both branches)
    convert_q<<<dim3(LQ, BB), 256>>>(x, q);
    convert_w<<<dim3((DD * DD) / 256, 2), 256>>>(W_a, W_v, W);
    prep_kv<<<dim3(DD / 32, LQ / 32, ZB), dim3(32, 8)>>>(x_a, x_v, kv, kT);

    // GEMM1: S[z,i,j] = scale * q[z&7,i,:].kv[z,j,:]  (M=2048,N=2048,K=768, z=16)
    mma_gemm<0><<<dim3(16, 16, ZB), GTHREADS, GEMM_SMEM>>>(
        q, kv, S, nullptr,
        DD, LQ, (long)LQ * DD, (long)LQ * DD, (long)LQ * LQ, QKSCALE, 7);

    softmax_f16<<<ZB * LQ, 256>>>(S, P);

    // GEMM2: ctx[z,i,d] = P[z,i,:].kvT[z,d,:]  (M=2048,N=768,K=2048, z=16)
    mma_gemm<1><<<dim3(6, 16, ZB), GTHREADS, GEMM_SMEM>>>(
        P, kT, nullptr, c,
        LQ, DD, (long)LQ * LQ, (long)DD * LQ, (long)LQ * DD, 1.f, 0xFF);

    // GEMM3: y[br,r,e] = ctx[br,r,:].W[br,e,:]  (M=16384,N=768,K=768, z=2)
    mma_gemm<0><<<dim3(6, 128, 2), GTHREADS, GEMM_SMEM>>>(
        c, W, y, nullptr,
        DD, DD, (long)MROWS * DD, (long)DD * DD, (long)MROWS * DD, 1.f, 0xFF);

    bn_partial<<<dim3(128, 2), 256>>>(y, part);
    bn_finalize<<<dim3(3, 2), 256>>>(part, bn_a_g, bn_a_b, bn_v_g, bn_v_b, stats);

    combine_ln<<<MROWS, 256>>>(x, y, stats, pre_a, pre_v, ln_g, ln_b, out);
}

// round 11
// speedup vs baseline: 2.2545x; 1.0841x over previous
#include <cuda_runtime.h>
#include <cuda_fp16.h>
#include <cstdint>

#define LQ 2048
#define BB 8
#define DD 768
#define MROWS (BB * LQ)
#define ZB (2 * BB)                 // branch*8 + batch
#define QKSCALE 0.0360843918243516f

using f16 = __half;

// ---------------------------------------------------------------------------
// Scratch (device globals; allocation-free per harness rules)
// ---------------------------------------------------------------------------
__device__ __align__(16) float g_S[(size_t)ZB * LQ * LQ];     // 256MB logits, both branches
__device__ __align__(16) f16   g_P[(size_t)ZB * LQ * LQ];     // softmax probs (fp16)
__device__ __align__(16) f16   g_q[(size_t)MROWS * DD];
__device__ __align__(16) f16   g_kv[(size_t)2 * MROWS * DD];
__device__ __align__(16) f16   g_kT[(size_t)2 * MROWS * DD];
__device__ __align__(16) f16   g_c[(size_t)2 * MROWS * DD];
__device__ __align__(16) f16   g_W[2 * DD * DD];
__device__ __align__(16) float g_y[(size_t)2 * MROWS * DD];   // conv out, both branches
__device__ float g_part[2 * 2 * 128 * DD];
__device__ float g_stats[2 * 2 * DD];

// ---------------------------------------------------------------------------
// Helpers (baseline PTX only: ldmatrix / mma.sync / cp.async)
// ---------------------------------------------------------------------------
__device__ __forceinline__ uint32_t smem_u32(const void* p) {
    uint32_t a;
    asm("{ .reg .u64 t; cvta.to.shared.u64 t, %1; cvt.u32.u64 %0, t; }" : "=r"(a) : "l"(p));
    return a;
}
__device__ __forceinline__ void cp16(uint32_t saddr, const void* gaddr) {
    asm volatile("cp.async.cg.shared.global [%0], [%1], 16;" :: "r"(saddr), "l"(gaddr));
}
#define CP_COMMIT() asm volatile("cp.async.commit_group;" ::: "memory")
#define CP_WAIT0()  asm volatile("cp.async.wait_group 0;" ::: "memory")
#define CP_WAIT1()  asm volatile("cp.async.wait_group 1;" ::: "memory")

__device__ __forceinline__ void ldmat_x4(uint32_t& r0, uint32_t& r1, uint32_t& r2,
                                         uint32_t& r3, uint32_t addr) {
    asm volatile("ldmatrix.sync.aligned.m8n8.x4.shared.b16 {%0,%1,%2,%3}, [%4];"
                 : "=r"(r0), "=r"(r1), "=r"(r2), "=r"(r3) : "r"(addr));
}
__device__ __forceinline__ void mma16816(float* c, uint32_t a0, uint32_t a1,
                                         uint32_t a2, uint32_t a3,
                                         uint32_t b0, uint32_t b1) {
    asm volatile(
        "mma.sync.aligned.m16n8k16.row.col.f32.f16.f16.f32 "
        "{%0,%1,%2,%3}, {%4,%5,%6,%7}, {%8,%9}, {%0,%1,%2,%3};"
        : "+f"(c[0]), "+f"(c[1]), "+f"(c[2]), "+f"(c[3])
        : "r"(a0), "r"(a1), "r"(a2), "r"(a3), "r"(b0), "r"(b1));
}

__device__ __forceinline__ uint32_t sw_off(int row, int kbyte) {
    uint32_t off = (uint32_t)row * 128u + (uint32_t)kbyte;
    return off ^ ((off >> 3) & 0x70u);
}
__device__ __forceinline__ uint32_t pack_h(float a, float b) {
    uint16_t ha = __half_as_ushort(__float2half(a));
    uint16_t hb = __half_as_ushort(__float2half(b));
    return (uint32_t)ha | ((uint32_t)hb << 16);
}

// ---------------------------------------------------------------------------
// fp16 warp-MMA GEMM: C[m,n] = alpha * sum_k A[m,k]*B[n,k]
// Pure fp16 operands, fp32 accumulate.
// 128x256 CTA tile, 256 threads / 8 warps (2x4 grid, 64x64 warp tiles),
// K in 64-chunks, 3-stage cp.async pipeline (48KB/stage: A 16KB + B 32KB).
// A batch index = z & amask; B/C batch index = z.
// OUTMODE 0: fp32 C.  OUTMODE 1: fp16 C.
// ---------------------------------------------------------------------------
#define STAGE_BYTES 49152
#define B_SM_OFF 16384
#define GEMM_SMEM (3 * STAGE_BYTES)
#define GTHREADS 256

__device__ __forceinline__ void stage_load(uint32_t sdst, const f16* __restrict__ A,
                                           const f16* __restrict__ B,
                                           int K, int k0, int t) {
#pragma unroll
    for (int i = 0; i < 4; i++) {         // A: 128 rows
        int idx = t + i * GTHREADS;       // 0..1023
        int row = idx >> 3, ch = idx & 7;
        cp16(sdst + sw_off(row, ch * 16), A + (size_t)row * K + k0 + ch * 8);
    }
#pragma unroll
    for (int i = 0; i < 8; i++) {         // B: 256 rows
        int idx = t + i * GTHREADS;       // 0..2047
        int row = idx >> 3, ch = idx & 7;
        cp16(sdst + B_SM_OFF + sw_off(row, ch * 16), B + (size_t)row * K + k0 + ch * 8);
    }
}

template<int OUTMODE>
__global__ void __launch_bounds__(GTHREADS, 1)
mma_gemm(const f16* __restrict__ A, const f16* __restrict__ B,
         float* __restrict__ C, f16* __restrict__ Ch,
         int K, int ldc, long sA, long sB, long sC, float alpha, int amask)
{
    extern __shared__ __align__(1024) char smem[];
    const uint32_t sb = smem_u32(smem);
    const int t = threadIdx.x, lane = t & 31, wid = t >> 5;
    const int wm = wid & 1, wn = wid >> 1;          // 2x4 warp grid, 64x64 tiles
    const int m0 = blockIdx.y * 128, n0 = blockIdx.x * 256, z = blockIdx.z;
    const int kiters = K >> 6;

    A += (size_t)(z & amask) * sA + (size_t)m0 * K;
    B += (size_t)z * sB + (size_t)n0 * K;

    float acc[4][8][4];
#pragma unroll
    for (int i = 0; i < 4; i++)
#pragma unroll
        for (int j = 0; j < 8; j++)
#pragma unroll
            for (int q = 0; q < 4; q++) acc[i][j][q] = 0.f;

    // ldmatrix lane-address components
    const int a_m_add = (lane & 7) + ((lane >> 3) & 1) * 8;
    const int a_k_add = ((lane >> 4) & 1) * 8;
    // B x4: matrices (0,1) = n-tile +0 @ k 0/8; matrices (2,3) = n-tile +8 @ k 0/8
    const int b_n_add = (lane & 7) + ((lane >> 4) << 3);
    const int b_k_add = ((lane >> 3) & 1) * 8;

    stage_load(sb, A, B, K, 0, t);
    CP_COMMIT();
    if (kiters > 1) {
        stage_load(sb + STAGE_BYTES, A, B, K, 64, t);
        CP_COMMIT();
    }

    uint32_t cur = 0;  // rotating stage index
    for (int it = 0; it < kiters; it++) {
        if (it + 1 < kiters) { CP_WAIT1(); } else { CP_WAIT0(); }
        __syncthreads();
        if (it + 2 < kiters) {
            uint32_t nxt = cur + 2; if (nxt >= 3) nxt -= 3;
            stage_load(sb + nxt * STAGE_BYTES, A, B, K, (it + 2) << 6, t);
            CP_COMMIT();
        }
        const uint32_t st = sb + cur * STAGE_BYTES;

#pragma unroll
        for (int ks = 0; ks < 4; ks++) {
            const int kb = ks * 16;
            uint32_t ah[4][4];
#pragma unroll
            for (int tm = 0; tm < 4; tm++) {
                int m = wm * 64 + tm * 16 + a_m_add;
                uint32_t so = sw_off(m, (kb + a_k_add) * 2);
                ldmat_x4(ah[tm][0], ah[tm][1], ah[tm][2], ah[tm][3], st + so);
            }
            uint32_t bh[8][2];
#pragma unroll
            for (int tn2 = 0; tn2 < 4; tn2++) {
                int n = wn * 64 + tn2 * 16 + b_n_add;
                uint32_t so = sw_off(n, (kb + b_k_add) * 2);
                ldmat_x4(bh[tn2 * 2][0], bh[tn2 * 2][1],
                         bh[tn2 * 2 + 1][0], bh[tn2 * 2 + 1][1], st + B_SM_OFF + so);
            }
#pragma unroll
            for (int tm = 0; tm < 4; tm++)
#pragma unroll
                for (int tn = 0; tn < 8; tn++)
                    mma16816(acc[tm][tn], ah[tm][0], ah[tm][1], ah[tm][2], ah[tm][3],
                             bh[tn][0], bh[tn][1]);
        }
        cur = cur + 1; if (cur >= 3) cur -= 3;
    }

    // Epilogue
    const int gid = lane >> 2, tig = lane & 3;
#pragma unroll
    for (int tm = 0; tm < 4; tm++) {
        const int r0 = m0 + wm * 64 + tm * 16 + gid;
#pragma unroll
        for (int tn = 0; tn < 8; tn++) {
            const int cN = n0 + wn * 64 + tn * 8 + tig * 2;
            float* a = acc[tm][tn];
            if (OUTMODE == 0) {
                *(float2*)(C + (size_t)z * sC + (size_t)r0 * ldc + cN) =
                    make_float2(a[0] * alpha, a[1] * alpha);
                *(float2*)(C + (size_t)z * sC + (size_t)(r0 + 8) * ldc + cN) =
                    make_float2(a[2] * alpha, a[3] * alpha);
            } else {
                *(uint32_t*)(Ch + (size_t)z * sC + (size_t)r0 * ldc + cN) = pack_h(a[0], a[1]);
                *(uint32_t*)(Ch + (size_t)z * sC + (size_t)(r0 + 8) * ldc + cN) = pack_h(a[2], a[3]);
            }
        }
    }
}

// ---------------------------------------------------------------------------
// Prep kernels
// ---------------------------------------------------------------------------
// x [L,B,D] -> q fp16 [B,L,D]
__global__ void convert_q(const float* __restrict__ in, f16* __restrict__ q)
{
    const int l = blockIdx.x, b = blockIdx.y, t = threadIdx.x;
    const float* s = in + (size_t)l * (BB * DD) + (size_t)b * DD;
    const size_t o = ((size_t)b * LQ + l) * DD;
#pragma unroll
    for (int j = 0; j < 3; j++)
        q[o + t + j * 256] = __float2half(s[t + j * 256]);
}

// W_a/W_v -> fp16
__global__ void convert_w(const float* __restrict__ wa, const float* __restrict__ wv,
                          f16* __restrict__ w)
{
    const int br = blockIdx.y;
    const int i = blockIdx.x * 256 + threadIdx.x;
    w[br * DD * DD + i] = __float2half((br ? wv : wa)[i]);
}

// x_a/x_v [L,B,D] -> kv fp16 [z][L][D] AND kvT fp16 [z][D][L], z = br*8+b
__global__ void prep_kv(const float* __restrict__ xa, const float* __restrict__ xv,
                        f16* __restrict__ kv, f16* __restrict__ kT)
{
    __shared__ uint16_t th[32][33];
    const int z = blockIdx.z, b = z & 7;
    const float* src = (z >> 3) ? xv : xa;
    const int d0 = blockIdx.x * 32, l0 = blockIdx.y * 32;
    const int tx = threadIdx.x, ty = threadIdx.y;
#pragma unroll
    for (int r = 0; r < 4; r++) {
        int l = l0 + ty + r * 8;
        float v = src[(size_t)l * (BB * DD) + (size_t)b * DD + d0 + tx];
        uint16_t h = __half_as_ushort(__float2half(v));
        kv[((size_t)z * LQ + l) * DD + d0 + tx] = __ushort_as_half(h);
        th[ty + r * 8][tx] = h;
    }
    __syncthreads();
#pragma unroll
    for (int r = 0; r < 4; r++) {
        int d = d0 + ty + r * 8;
        kT[((size_t)z * DD + d) * LQ + l0 + tx] = __ushort_as_half(th[tx][ty + r * 8]);
    }
}

// ---------------------------------------------------------------------------
// Softmax over 2048-wide rows -> fp16 probs. grid = ZB*LQ, block = 256.
// ---------------------------------------------------------------------------
__global__ void softmax_f16(const float* __restrict__ S, f16* __restrict__ P)
{
    __shared__ float red[8];
    const float* p = S + (size_t)blockIdx.x * 2048;
    const int t = threadIdx.x;

    float4 v0 = ((const float4*)p)[t];
    float4 v1 = ((const float4*)p)[t + 256];

    float m = fmaxf(fmaxf(fmaxf(v0.x, v0.y), fmaxf(v0.z, v0.w)),
                    fmaxf(fmaxf(v1.x, v1.y), fmaxf(v1.z, v1.w)));
#pragma unroll
    for (int o = 16; o; o >>= 1) m = fmaxf(m, __shfl_xor_sync(~0u, m, o));
    if ((t & 31) == 0) red[t >> 5] = m;
    __syncthreads();
    float mx = red[0];
#pragma unroll
    for (int w = 1; w < 8; w++) mx = fmaxf(mx, red[w]);
    __syncthreads();

    v0.x = __expf(v0.x - mx); v0.y = __expf(v0.y - mx);
    v0.z = __expf(v0.z - mx); v0.w = __expf(v0.w - mx);
    v1.x = __expf(v1.x - mx); v1.y = __expf(v1.y - mx);
    v1.z = __expf(v1.z - mx); v1.w = __expf(v1.w - mx);

    float s = v0.x + v0.y + v0.z + v0.w + v1.x + v1.y + v1.z + v1.w;
#pragma unroll
    for (int o = 16; o; o >>= 1) s += __shfl_xor_sync(~0u, s, o);
    if ((t & 31) == 0) red[t >> 5] = s;
    __syncthreads();
    float sm = 0.f;
#pragma unroll
    for (int w = 0; w < 8; w++) sm += red[w];
    const float inv = 1.f / sm;

    v0.x *= inv; v0.y *= inv; v0.z *= inv; v0.w *= inv;
    v1.x *= inv; v1.y *= inv; v1.z *= inv; v1.w *= inv;

    const size_t base = (size_t)blockIdx.x * 2048;
    ((uint2*)(P + base))[t] = make_uint2(pack_h(v0.x, v0.y), pack_h(v0.z, v0.w));
    ((uint2*)(P + base))[t + 256] = make_uint2(pack_h(v1.x, v1.y), pack_h(v1.z, v1.w));
}

// ---------------------------------------------------------------------------
// BatchNorm stats (two-stage, deterministic; grid.y = branch)
// ---------------------------------------------------------------------------
__global__ void bn_partial(const float* __restrict__ yAll, float* __restrict__ partAll)
{
    const int br = blockIdx.y, t = threadIdx.x;
    const float* base = yAll + (size_t)br * MROWS * DD + (size_t)blockIdx.x * 128 * DD;
    float* part = partAll + (size_t)br * 2 * 128 * DD;
    float s[3] = {0.f, 0.f, 0.f}, q[3] = {0.f, 0.f, 0.f};
    for (int r = 0; r < 128; r++) {
        const float* row = base + (size_t)r * DD;
#pragma unroll
        for (int j = 0; j < 3; j++) {
            float v = row[t + j * 256];
            s[j] += v; q[j] += v * v;
        }
    }
#pragma unroll
    for (int j = 0; j < 3; j++) {
        part[blockIdx.x * DD + t + j * 256] = s[j];
        part[128 * DD + blockIdx.x * DD + t + j * 256] = q[j];
    }
}

__global__ void bn_finalize(const float* __restrict__ partAll,
                            const float* __restrict__ ga, const float* __restrict__ ba,
                            const float* __restrict__ gv, const float* __restrict__ bv,
                            float* __restrict__ statsAll)
{
    const int br = blockIdx.y;
    const int c = blockIdx.x * 256 + threadIdx.x;
    const float* part = partAll + (size_t)br * 2 * 128 * DD;
    const float* gamma = br ? gv : ga;
    const float* beta  = br ? bv : ba;
    float* statsOut = statsAll + br * 2 * DD;
    float s = 0.f, q = 0.f;
    for (int k = 0; k < 128; k++) {
        s += part[k * DD + c];
        q += part[128 * DD + k * DD + c];
    }
    const float mean = s * (1.f / (float)MROWS);
    const float var  = q * (1.f / (float)MROWS) - mean * mean;
    const float scale = gamma[c] * rsqrtf(var + 1e-5f);
    statsOut[c]      = scale;
    statsOut[DD + c] = beta[c] - mean * scale;
}

// ---------------------------------------------------------------------------
// Combine: BN-apply + PReLU + residual + LayerNorm. grid = MROWS.
// ---------------------------------------------------------------------------
__global__ void combine_ln(const float* __restrict__ x,
                           const float* __restrict__ yAll,
                           const float* __restrict__ stats,
                           const float* __restrict__ pa,
                           const float* __restrict__ pv,
                           const float* __restrict__ lng,
                           const float* __restrict__ lnb,
                           float* __restrict__ out)
{
    __shared__ float rs[8], rq[8];
    const int pos = blockIdx.x;
    const int b = pos >> 11, l = pos & 2047;
    const size_t yoff = (size_t)pos * DD;
    const size_t xoff = (size_t)l * (BB * DD) + (size_t)b * DD;
    const int t = threadIdx.x;
    const float aa = pa[0], av = pv[0];
    const float* ya = yAll;
    const float* yv = yAll + (size_t)MROWS * DD;

    float vv[3];
    float s = 0.f, q = 0.f;
#pragma unroll
    for (int j = 0; j < 3; j++) {
        const int d = t + j * 256;
        float va = ya[yoff + d] * stats[d] + stats[DD + d];
        va = va > 0.f ? va : aa * va;
        float vb = yv[yoff + d] * stats[2 * DD + d] + stats[3 * DD + d];
        vb = vb > 0.f ? vb : av * vb;
        float val = x[xoff + d] + va + vb;
        vv[j] = val; s += val; q += val * val;
    }
#pragma unroll
    for (int o = 16; o; o >>= 1) {
        s += __shfl_xor_sync(~0u, s, o);
        q += __shfl_xor_sync(~0u, q, o);
    }
    if ((t & 31) == 0) { rs[t >> 5] = s; rq[t >> 5] = q; }
    __syncthreads();
    s = 0.f; q = 0.f;
#pragma unroll
    for (int w = 0; w < 8; w++) { s += rs[w]; q += rq[w]; }
    const float mean = s * (1.f / (float)DD);
    const float var  = q * (1.f / (float)DD) - mean * mean;
    const float rstd = rsqrtf(var + 1e-5f);
#pragma unroll
    for (int j = 0; j < 3; j++) {
        const int d = t + j * 256;
        out[xoff + d] = (vv[j] - mean) * rstd * lng[d] + lnb[d];
    }
}

// ---------------------------------------------------------------------------
// Host orchestration (graph-capturable)
// ---------------------------------------------------------------------------
extern "C" void kernel_launch(void* const* d_in, const int* in_sizes, int n_in,
                              void* d_out, int out_size)
{
    const float* x_a    = (const float*)d_in[0];
    const float* x_v    = (const float*)d_in[1];
    const float* x      = (const float*)d_in[2];
    const float* W_a    = (const float*)d_in[3];
    const float* bn_a_g = (const float*)d_in[5];
    const float* bn_a_b = (const float*)d_in[6];
    const float* pre_a  = (const float*)d_in[7];
    const float* W_v    = (const float*)d_in[8];
    const float* bn_v_g = (const float*)d_in[10];
    const float* bn_v_b = (const float*)d_in[11];
    const float* pre_v  = (const float*)d_in[12];
    const float* ln_g   = (const float*)d_in[13];
    const float* ln_b   = (const float*)d_in[14];
    float* out = (float*)d_out;

    float *S, *y, *part, *stats;
    f16 *P, *q, *kv, *kT, *c, *W;
    cudaGetSymbolAddress((void**)&S,    g_S);
    cudaGetSymbolAddress((void**)&P,    g_P);
    cudaGetSymbolAddress((void**)&q,    g_q);
    cudaGetSymbolAddress((void**)&kv,   g_kv);
    cudaGetSymbolAddress((void**)&kT,   g_kT);
    cudaGetSymbolAddress((void**)&c,    g_c);
    cudaGetSymbolAddress((void**)&W,    g_W);
    cudaGetSymbolAddress((void**)&y,    g_y);
    cudaGetSymbolAddress((void**)&part, g_part);
    cudaGetSymbolAddress((void**)&stats, g_stats);

    cudaFuncSetAttribute(mma_gemm<0>, cudaFuncAttributeMaxDynamicSharedMemorySize, GEMM_SMEM);
    cudaFuncSetAttribute(mma_gemm<1>, cudaFuncAttributeMaxDynamicSharedMemorySize, GEMM_SMEM);

    // Prep: q, W, kv/kvT (both branches)
    convert_q<<<dim3(LQ, BB), 256>>>(x, q);
    convert_w<<<dim3((DD * DD) / 256, 2), 256>>>(W_a, W_v, W);
    prep_kv<<<dim3(DD / 32, LQ / 32, ZB), dim3(32, 8)>>>(x_a, x_v, kv, kT);

    // GEMM1: S[z,i,j] = scale * q[z&7,i,:].kv[z,j,:]  (M=2048,N=2048,K=768, z=16)
    mma_gemm<0><<<dim3(8, 16, ZB), GTHREADS, GEMM_SMEM>>>(
        q, kv, S, nullptr,
        DD, LQ, (long)LQ * DD, (long)LQ * DD, (long)LQ * LQ, QKSCALE, 7);

    softmax_f16<<<ZB * LQ, 256>>>(S, P);

    // GEMM2: ctx[z,i,d] = P[z,i,:].kvT[z,d,:]  (M=2048,N=768,K=2048, z=16)
    mma_gemm<1><<<dim3(3, 16, ZB), GTHREADS, GEMM_SMEM>>>(
        P, kT, nullptr, c,
        LQ, DD, (long)LQ * LQ, (long)DD * LQ, (long)LQ * DD, 1.f, 0xFF);

    // GEMM3: y[br,r,e] = ctx[br,r,:].W[br,e,:]  (M=16384,N=768,K=768, z=2)
    mma_gemm<0><<<dim3(3, 128, 2), GTHREADS, GEMM_SMEM>>>(
        c, W, y, nullptr,
        DD, DD, (long)MROWS * DD, (long)DD * DD, (long)MROWS * DD, 1.f, 0xFF);

    bn_partial<<<dim3(128, 2), 256>>>(y, part);
    bn_finalize<<<dim3(3, 2), 256>>>(part, bn_a_g, bn_a_b, bn_v_g, bn_v_b, stats);

    combine_ln<<<MROWS, 256>>>(x, y, stats, pre_a, pre_v, ln_g, ln_b, out);
}

// round 12
// speedup vs baseline: 2.3190x; 1.0286x over previous
#include <cuda_runtime.h>
#include <cuda_fp16.h>
#include <cstdint>

#define LQ 2048
#define BB 8
#define DD 768
#define MROWS (BB * LQ)
#define ZB (2 * BB)                 // branch*8 + batch
#define QKSCALE 0.0360843918243516f

using f16 = __half;

// ---------------------------------------------------------------------------
// Scratch (device globals; allocation-free per harness rules)
// ---------------------------------------------------------------------------
__device__ __align__(16) f16   g_S[(size_t)ZB * LQ * LQ];     // 128MB logits->probs (in-place)
__device__ __align__(16) f16   g_q[(size_t)MROWS * DD];
__device__ __align__(16) f16   g_kv[(size_t)2 * MROWS * DD];
__device__ __align__(16) f16   g_kT[(size_t)2 * MROWS * DD];
__device__ __align__(16) f16   g_c[(size_t)2 * MROWS * DD];
__device__ __align__(16) f16   g_W[2 * DD * DD];
__device__ __align__(16) f16   g_y[(size_t)2 * MROWS * DD];   // conv out fp16, both branches
__device__ float g_part[2 * 2 * 128 * DD];
__device__ float g_stats[2 * 2 * DD];

// ---------------------------------------------------------------------------
// Helpers (baseline PTX only: ldmatrix / mma.sync / cp.async)
// ---------------------------------------------------------------------------
__device__ __forceinline__ uint32_t smem_u32(const void* p) {
    uint32_t a;
    asm("{ .reg .u64 t; cvta.to.shared.u64 t, %1; cvt.u32.u64 %0, t; }" : "=r"(a) : "l"(p));
    return a;
}
__device__ __forceinline__ void cp16(uint32_t saddr, const void* gaddr) {
    asm volatile("cp.async.cg.shared.global [%0], [%1], 16;" :: "r"(saddr), "l"(gaddr));
}
#define CP_COMMIT() asm volatile("cp.async.commit_group;" ::: "memory")
#define CP_WAIT0()  asm volatile("cp.async.wait_group 0;" ::: "memory")
#define CP_WAIT1()  asm volatile("cp.async.wait_group 1;" ::: "memory")

__device__ __forceinline__ void ldmat_x4(uint32_t& r0, uint32_t& r1, uint32_t& r2,
                                         uint32_t& r3, uint32_t addr) {
    asm volatile("ldmatrix.sync.aligned.m8n8.x4.shared.b16 {%0,%1,%2,%3}, [%4];"
                 : "=r"(r0), "=r"(r1), "=r"(r2), "=r"(r3) : "r"(addr));
}
__device__ __forceinline__ void mma16816(float* c, uint32_t a0, uint32_t a1,
                                         uint32_t a2, uint32_t a3,
                                         uint32_t b0, uint32_t b1) {
    asm volatile(
        "mma.sync.aligned.m16n8k16.row.col.f32.f16.f16.f32 "
        "{%0,%1,%2,%3}, {%4,%5,%6,%7}, {%8,%9}, {%0,%1,%2,%3};"
        : "+f"(c[0]), "+f"(c[1]), "+f"(c[2]), "+f"(c[3])
        : "r"(a0), "r"(a1), "r"(a2), "r"(a3), "r"(b0), "r"(b1));
}

__device__ __forceinline__ uint32_t sw_off(int row, int kbyte) {
    uint32_t off = (uint32_t)row * 128u + (uint32_t)kbyte;
    return off ^ ((off >> 3) & 0x70u);
}
__device__ __forceinline__ uint32_t pack_h(float a, float b) {
    __half2 h = __float22half2_rn(make_float2(a, b));
    return *(uint32_t*)&h;
}

// ---------------------------------------------------------------------------
// fp16 warp-MMA GEMM: C[m,n] = alpha * sum_k A[m,k]*B[n,k]
// Pure fp16 operands, fp32 accumulate.
// 128x256 CTA tile, 256 threads / 8 warps (2x4 grid, 64x64 warp tiles),
// K in 64-chunks, 3-stage cp.async pipeline (48KB/stage: A 16KB + B 32KB).
// A batch index = z & amask; B/C batch index = z.
// OUTMODE 0: fp32 C.  OUTMODE 1: fp16 C (alpha applied).
// ---------------------------------------------------------------------------
#define STAGE_BYTES 49152
#define B_SM_OFF 16384
#define GEMM_SMEM (3 * STAGE_BYTES)
#define GTHREADS 256

__device__ __forceinline__ void stage_load(uint32_t sdst, const f16* __restrict__ A,
                                           const f16* __restrict__ B,
                                           int K, int k0, int t) {
#pragma unroll
    for (int i = 0; i < 4; i++) {         // A: 128 rows
        int idx = t + i * GTHREADS;       // 0..1023
        int row = idx >> 3, ch = idx & 7;
        cp16(sdst + sw_off(row, ch * 16), A + (size_t)row * K + k0 + ch * 8);
    }
#pragma unroll
    for (int i = 0; i < 8; i++) {         // B: 256 rows
        int idx = t + i * GTHREADS;       // 0..2047
        int row = idx >> 3, ch = idx & 7;
        cp16(sdst + B_SM_OFF + sw_off(row, ch * 16), B + (size_t)row * K + k0 + ch * 8);
    }
}

template<int OUTMODE>
__global__ void __launch_bounds__(GTHREADS, 1)
mma_gemm(const f16* __restrict__ A, const f16* __restrict__ B,
         float* __restrict__ C, f16* __restrict__ Ch,
         int K, int ldc, long sA, long sB, long sC, float alpha, int amask)
{
    extern __shared__ __align__(1024) char smem[];
    const uint32_t sb = smem_u32(smem);
    const int t = threadIdx.x, lane = t & 31, wid = t >> 5;
    const int wm = wid & 1, wn = wid >> 1;          // 2x4 warp grid, 64x64 tiles
    const int m0 = blockIdx.y * 128, n0 = blockIdx.x * 256, z = blockIdx.z;
    const int kiters = K >> 6;

    A += (size_t)(z & amask) * sA + (size_t)m0 * K;
    B += (size_t)z * sB + (size_t)n0 * K;

    float acc[4][8][4];
#pragma unroll
    for (int i = 0; i < 4; i++)
#pragma unroll
        for (int j = 0; j < 8; j++)
#pragma unroll
            for (int q = 0; q < 4; q++) acc[i][j][q] = 0.f;

    // ldmatrix lane-address components
    const int a_m_add = (lane & 7) + ((lane >> 3) & 1) * 8;
    const int a_k_add = ((lane >> 4) & 1) * 8;
    // B x4: matrices (0,1) = n-tile +0 @ k 0/8; matrices (2,3) = n-tile +8 @ k 0/8
    const int b_n_add = (lane & 7) + ((lane >> 4) << 3);
    const int b_k_add = ((lane >> 3) & 1) * 8;

    stage_load(sb, A, B, K, 0, t);
    CP_COMMIT();
    if (kiters > 1) {
        stage_load(sb + STAGE_BYTES, A, B, K, 64, t);
        CP_COMMIT();
    }

    uint32_t cur = 0;  // rotating stage index
    for (int it = 0; it < kiters; it++) {
        if (it + 1 < kiters) { CP_WAIT1(); } else { CP_WAIT0(); }
        __syncthreads();
        if (it + 2 < kiters) {
            uint32_t nxt = cur + 2; if (nxt >= 3) nxt -= 3;
            stage_load(sb + nxt * STAGE_BYTES, A, B, K, (it + 2) << 6, t);
            CP_COMMIT();
        }
        const uint32_t st = sb + cur * STAGE_BYTES;

#pragma unroll
        for (int ks = 0; ks < 4; ks++) {
            const int kb = ks * 16;
            uint32_t ah[4][4];
#pragma unroll
            for (int tm = 0; tm < 4; tm++) {
                int m = wm * 64 + tm * 16 + a_m_add;
                uint32_t so = sw_off(m, (kb + a_k_add) * 2);
                ldmat_x4(ah[tm][0], ah[tm][1], ah[tm][2], ah[tm][3], st + so);
            }
            uint32_t bh[8][2];
#pragma unroll
            for (int tn2 = 0; tn2 < 4; tn2++) {
                int n = wn * 64 + tn2 * 16 + b_n_add;
                uint32_t so = sw_off(n, (kb + b_k_add) * 2);
                ldmat_x4(bh[tn2 * 2][0], bh[tn2 * 2][1],
                         bh[tn2 * 2 + 1][0], bh[tn2 * 2 + 1][1], st + B_SM_OFF + so);
            }
#pragma unroll
            for (int tm = 0; tm < 4; tm++)
#pragma unroll
                for (int tn = 0; tn < 8; tn++)
                    mma16816(acc[tm][tn], ah[tm][0], ah[tm][1], ah[tm][2], ah[tm][3],
                             bh[tn][0], bh[tn][1]);
        }
        cur = cur + 1; if (cur >= 3) cur -= 3;
    }

    // Epilogue
    const int gid = lane >> 2, tig = lane & 3;
#pragma unroll
    for (int tm = 0; tm < 4; tm++) {
        const int r0 = m0 + wm * 64 + tm * 16 + gid;
#pragma unroll
        for (int tn = 0; tn < 8; tn++) {
            const int cN = n0 + wn * 64 + tn * 8 + tig * 2;
            float* a = acc[tm][tn];
            if (OUTMODE == 0) {
                *(float2*)(C + (size_t)z * sC + (size_t)r0 * ldc + cN) =
                    make_float2(a[0] * alpha, a[1] * alpha);
                *(float2*)(C + (size_t)z * sC + (size_t)(r0 + 8) * ldc + cN) =
                    make_float2(a[2] * alpha, a[3] * alpha);
            } else {
                *(uint32_t*)(Ch + (size_t)z * sC + (size_t)r0 * ldc + cN) =
                    pack_h(a[0] * alpha, a[1] * alpha);
                *(uint32_t*)(Ch + (size_t)z * sC + (size_t)(r0 + 8) * ldc + cN) =
                    pack_h(a[2] * alpha, a[3] * alpha);
            }
        }
    }
}

// ---------------------------------------------------------------------------
// Prep kernels
// ---------------------------------------------------------------------------
// x [L,B,D] -> q fp16 [B,L,D]
__global__ void convert_q(const float* __restrict__ in, f16* __restrict__ q)
{
    const int l = blockIdx.x, b = blockIdx.y, t = threadIdx.x;
    const float* s = in + (size_t)l * (BB * DD) + (size_t)b * DD;
    const size_t o = ((size_t)b * LQ + l) * DD;
#pragma unroll
    for (int j = 0; j < 3; j++)
        q[o + t + j * 256] = __float2half(s[t + j * 256]);
}

// W_a/W_v -> fp16
__global__ void convert_w(const float* __restrict__ wa, const float* __restrict__ wv,
                          f16* __restrict__ w)
{
    const int br = blockIdx.y;
    const int i = blockIdx.x * 256 + threadIdx.x;
    w[br * DD * DD + i] = __float2half((br ? wv : wa)[i]);
}

// x_a/x_v [L,B,D] -> kv fp16 [z][L][D] AND kvT fp16 [z][D][L], z = br*8+b
__global__ void prep_kv(const float* __restrict__ xa, const float* __restrict__ xv,
                        f16* __restrict__ kv, f16* __restrict__ kT)
{
    __shared__ uint16_t th[32][33];
    const int z = blockIdx.z, b = z & 7;
    const float* src = (z >> 3) ? xv : xa;
    const int d0 = blockIdx.x * 32, l0 = blockIdx.y * 32;
    const int tx = threadIdx.x, ty = threadIdx.y;
#pragma unroll
    for (int r = 0; r < 4; r++) {
        int l = l0 + ty + r * 8;
        float v = src[(size_t)l * (BB * DD) + (size_t)b * DD + d0 + tx];
        uint16_t h = __half_as_ushort(__float2half(v));
        kv[((size_t)z * LQ + l) * DD + d0 + tx] = __ushort_as_half(h);
        th[ty + r * 8][tx] = h;
    }
    __syncthreads();
#pragma unroll
    for (int r = 0; r < 4; r++) {
        int d = d0 + ty + r * 8;
        kT[((size_t)z * DD + d) * LQ + l0 + tx] = __ushort_as_half(th[tx][ty + r * 8]);
    }
}

// ---------------------------------------------------------------------------
// In-place softmax over 2048-wide fp16 rows. grid = ZB*LQ, block = 256.
// Each thread holds 8 values (one uint4 of 8 halfs).
// ---------------------------------------------------------------------------
__global__ void softmax_f16ip(f16* __restrict__ S)
{
    __shared__ float red[8];
    f16* row = S + (size_t)blockIdx.x * 2048;
    const int t = threadIdx.x;

    uint4 raw = ((const uint4*)row)[t];
    float v[8];
    {
        uint32_t w[4] = {raw.x, raw.y, raw.z, raw.w};
#pragma unroll
        for (int i = 0; i < 4; i++) {
            __half2 hh = *(__half2*)&w[i];
            float2 f = __half22float2(hh);
            v[2 * i] = f.x; v[2 * i + 1] = f.y;
        }
    }

    float m = v[0];
#pragma unroll
    for (int i = 1; i < 8; i++) m = fmaxf(m, v[i]);
#pragma unroll
    for (int o = 16; o; o >>= 1) m = fmaxf(m, __shfl_xor_sync(~0u, m, o));
    if ((t & 31) == 0) red[t >> 5] = m;
    __syncthreads();
    float mx = red[0];
#pragma unroll
    for (int w = 1; w < 8; w++) mx = fmaxf(mx, red[w]);
    __syncthreads();

    float s = 0.f;
#pragma unroll
    for (int i = 0; i < 8; i++) { v[i] = __expf(v[i] - mx); s += v[i]; }
#pragma unroll
    for (int o = 16; o; o >>= 1) s += __shfl_xor_sync(~0u, s, o);
    if ((t & 31) == 0) red[t >> 5] = s;
    __syncthreads();
    float sm = 0.f;
#pragma unroll
    for (int w = 0; w < 8; w++) sm += red[w];
    const float inv = 1.f / sm;

    uint4 outw;
    outw.x = pack_h(v[0] * inv, v[1] * inv);
    outw.y = pack_h(v[2] * inv, v[3] * inv);
    outw.z = pack_h(v[4] * inv, v[5] * inv);
    outw.w = pack_h(v[6] * inv, v[7] * inv);
    ((uint4*)row)[t] = outw;
}

// ---------------------------------------------------------------------------
// BatchNorm stats (two-stage, deterministic; grid.y = branch) — fp16 y input
// ---------------------------------------------------------------------------
__global__ void bn_partial(const f16* __restrict__ yAll, float* __restrict__ partAll)
{
    const int br = blockIdx.y, t = threadIdx.x;
    const f16* base = yAll + (size_t)br * MROWS * DD + (size_t)blockIdx.x * 128 * DD;
    float* part = partAll + (size_t)br * 2 * 128 * DD;
    float s[3] = {0.f, 0.f, 0.f}, q[3] = {0.f, 0.f, 0.f};
    for (int r = 0; r < 128; r++) {
        const f16* row = base + (size_t)r * DD;
#pragma unroll
        for (int j = 0; j < 3; j++) {
            float v = __half2float(row[t + j * 256]);
            s[j] += v; q[j] += v * v;
        }
    }
#pragma unroll
    for (int j = 0; j < 3; j++) {
        part[blockIdx.x * DD + t + j * 256] = s[j];
        part[128 * DD + blockIdx.x * DD + t + j * 256] = q[j];
    }
}

__global__ void bn_finalize(const float* __restrict__ partAll,
                            const float* __restrict__ ga, const float* __restrict__ ba,
                            const float* __restrict__ gv, const float* __restrict__ bv,
                            float* __restrict__ statsAll)
{
    const int br = blockIdx.y;
    const int c = blockIdx.x * 256 + threadIdx.x;
    const float* part = partAll + (size_t)br * 2 * 128 * DD;
    const float* gamma = br ? gv : ga;
    const float* beta  = br ? bv : ba;
    float* statsOut = statsAll + br * 2 * DD;
    float s = 0.f, q = 0.f;
    for (int k = 0; k < 128; k++) {
        s += part[k * DD + c];
        q += part[128 * DD + k * DD + c];
    }
    const float mean = s * (1.f / (float)MROWS);
    const float var  = q * (1.f / (float)MROWS) - mean * mean;
    const float scale = gamma[c] * rsqrtf(var + 1e-5f);
    statsOut[c]      = scale;
    statsOut[DD + c] = beta[c] - mean * scale;
}

// ---------------------------------------------------------------------------
// Combine: BN-apply + PReLU + residual + LayerNorm. grid = MROWS. fp16 y input
// ---------------------------------------------------------------------------
__global__ void combine_ln(const float* __restrict__ x,
                           const f16* __restrict__ yAll,
                           const float* __restrict__ stats,
                           const float* __restrict__ pa,
                           const float* __restrict__ pv,
                           const float* __restrict__ lng,
                           const float* __restrict__ lnb,
                           float* __restrict__ out)
{
    __shared__ float rs[8], rq[8];
    const int pos = blockIdx.x;
    const int b = pos >> 11, l = pos & 2047;
    const size_t yoff = (size_t)pos * DD;
    const size_t xoff = (size_t)l * (BB * DD) + (size_t)b * DD;
    const int t = threadIdx.x;
    const float aa = pa[0], av = pv[0];
    const f16* ya = yAll;
    const f16* yv = yAll + (size_t)MROWS * DD;

    float vv[3];
    float s = 0.f, q = 0.f;
#pragma unroll
    for (int j = 0; j < 3; j++) {
        const int d = t + j * 256;
        float va = __half2float(ya[yoff + d]) * stats[d] + stats[DD + d];
        va = va > 0.f ? va : aa * va;
        float vb = __half2float(yv[yoff + d]) * stats[2 * DD + d] + stats[3 * DD + d];
        vb = vb > 0.f ? vb : av * vb;
        float val = x[xoff + d] + va + vb;
        vv[j] = val; s += val; q += val * val;
    }
#pragma unroll
    for (int o = 16; o; o >>= 1) {
        s += __shfl_xor_sync(~0u, s, o);
        q += __shfl_xor_sync(~0u, q, o);
    }
    if ((t & 31) == 0) { rs[t >> 5] = s; rq[t >> 5] = q; }
    __syncthreads();
    s = 0.f; q = 0.f;
#pragma unroll
    for (int w = 0; w < 8; w++) { s += rs[w]; q += rq[w]; }
    const float mean = s * (1.f / (float)DD);
    const float var  = q * (1.f / (float)DD) - mean * mean;
    const float rstd = rsqrtf(var + 1e-5f);
#pragma unroll
    for (int j = 0; j < 3; j++) {
        const int d = t + j * 256;
        out[xoff + d] = (vv[j] - mean) * rstd * lng[d] + lnb[d];
    }
}

// ---------------------------------------------------------------------------
// Host orchestration (graph-capturable)
// ---------------------------------------------------------------------------
extern "C" void kernel_launch(void* const* d_in, const int* in_sizes, int n_in,
                              void* d_out, int out_size)
{
    const float* x_a    = (const float*)d_in[0];
    const float* x_v    = (const float*)d_in[1];
    const float* x      = (const float*)d_in[2];
    const float* W_a    = (const float*)d_in[3];
    const float* bn_a_g = (const float*)d_in[5];
    const float* bn_a_b = (const float*)d_in[6];
    const float* pre_a  = (const float*)d_in[7];
    const float* W_v    = (const float*)d_in[8];
    const float* bn_v_g = (const float*)d_in[10];
    const float* bn_v_b = (const float*)d_in[11];
    const float* pre_v  = (const float*)d_in[12];
    const float* ln_g   = (const float*)d_in[13];
    const float* ln_b   = (const float*)d_in[14];
    float* out = (float*)d_out;

    float *part, *stats;
    f16 *S, *q, *kv, *kT, *c, *W, *y;
    cudaGetSymbolAddress((void**)&S,    g_S);
    cudaGetSymbolAddress((void**)&q,    g_q);
    cudaGetSymbolAddress((void**)&kv,   g_kv);
    cudaGetSymbolAddress((void**)&kT,   g_kT);
    cudaGetSymbolAddress((void**)&c,    g_c);
    cudaGetSymbolAddress((void**)&W,    g_W);
    cudaGetSymbolAddress((void**)&y,    g_y);
    cudaGetSymbolAddress((void**)&part, g_part);
    cudaGetSymbolAddress((void**)&stats, g_stats);

    cudaFuncSetAttribute(mma_gemm<0>, cudaFuncAttributeMaxDynamicSharedMemorySize, GEMM_SMEM);
    cudaFuncSetAttribute(mma_gemm<1>, cudaFuncAttributeMaxDynamicSharedMemorySize, GEMM_SMEM);

    // Prep: q, W, kv/kvT (both branches)
    convert_q<<<dim3(LQ, BB), 256>>>(x, q);
    convert_w<<<dim3((DD * DD) / 256, 2), 256>>>(W_a, W_v, W);
    prep_kv<<<dim3(DD / 32, LQ / 32, ZB), dim3(32, 8)>>>(x_a, x_v, kv, kT);

    // GEMM1: S[z,i,j] = scale * q[z&7,i,:].kv[z,j,:]  -> fp16 logits (scale folded)
    mma_gemm<1><<<dim3(8, 16, ZB), GTHREADS, GEMM_SMEM>>>(
        q, kv, nullptr, S,
        DD, LQ, (long)LQ * DD, (long)LQ * DD, (long)LQ * LQ, QKSCALE, 7);

    // In-place softmax: fp16 logits -> fp16 probs
    softmax_f16ip<<<ZB * LQ, 256>>>(S);

    // GEMM2: ctx[z,i,d] = P[z,i,:].kvT[z,d,:]  -> fp16 ctx
    mma_gemm<1><<<dim3(3, 16, ZB), GTHREADS, GEMM_SMEM>>>(
        S, kT, nullptr, c,
        LQ, DD, (long)LQ * LQ, (long)DD * LQ, (long)LQ * DD, 1.f, 0xFF);

    // GEMM3: y[br,r,e] = ctx[br,r,:].W[br,e,:]  -> fp16 y (bias cancels in BN)
    mma_gemm<1><<<dim3(3, 128, 2), GTHREADS, GEMM_SMEM>>>(
        c, W, nullptr, y,
        DD, DD, (long)MROWS * DD, (long)DD * DD, (long)MROWS * DD, 1.f, 0xFF);

    bn_partial<<<dim3(128, 2), 256>>>(y, part);
    bn_finalize<<<dim3(3, 2), 256>>>(part, bn_a_g, bn_a_b, bn_v_g, bn_v_b, stats);

    combine_ln<<<MROWS, 256>>>(x, y, stats, pre_a, pre_v, ln_g, ln_b, out);
}

// round 13
// speedup vs baseline: 2.6048x; 1.1233x over previous
#include <cuda_runtime.h>
#include <cuda_fp16.h>
#include <cstdint>

#define LQ 2048
#define BB 8
#define DD 768
#define MROWS (BB * LQ)
#define ZB (2 * BB)                 // branch*8 + batch
#define QKSCALE 0.0360843918243516f

using f16 = __half;

// ---------------------------------------------------------------------------
// Scratch (device globals; allocation-free per harness rules)
// ---------------------------------------------------------------------------
__device__ __align__(16) f16   g_S[(size_t)ZB * LQ * LQ];     // 128MB logits->probs (in-place)
__device__ __align__(16) f16   g_q[(size_t)MROWS * DD];
__device__ __align__(16) f16   g_kv[(size_t)2 * MROWS * DD];
__device__ __align__(16) f16   g_kT[(size_t)2 * MROWS * DD];
__device__ __align__(16) f16   g_c[(size_t)2 * MROWS * DD];
__device__ __align__(16) f16   g_W[2 * DD * DD];
__device__ __align__(16) f16   g_y[(size_t)2 * MROWS * DD];   // conv out fp16, both branches
__device__ float g_part[2 * 2 * 128 * DD];
__device__ float g_stats[2 * 2 * DD];

// ---------------------------------------------------------------------------
// Helpers (baseline PTX only: ldmatrix / mma.sync / cp.async)
// ---------------------------------------------------------------------------
__device__ __forceinline__ uint32_t smem_u32(const void* p) {
    uint32_t a;
    asm("{ .reg .u64 t; cvta.to.shared.u64 t, %1; cvt.u32.u64 %0, t; }" : "=r"(a) : "l"(p));
    return a;
}
__device__ __forceinline__ void cp16(uint32_t saddr, const void* gaddr) {
    asm volatile("cp.async.cg.shared.global [%0], [%1], 16;" :: "r"(saddr), "l"(gaddr));
}
#define CP_COMMIT() asm volatile("cp.async.commit_group;" ::: "memory")
#define CP_WAIT0()  asm volatile("cp.async.wait_group 0;" ::: "memory")
#define CP_WAIT1()  asm volatile("cp.async.wait_group 1;" ::: "memory")

__device__ __forceinline__ void ldmat_x4(uint32_t& r0, uint32_t& r1, uint32_t& r2,
                                         uint32_t& r3, uint32_t addr) {
    asm volatile("ldmatrix.sync.aligned.m8n8.x4.shared.b16 {%0,%1,%2,%3}, [%4];"
                 : "=r"(r0), "=r"(r1), "=r"(r2), "=r"(r3) : "r"(addr));
}
__device__ __forceinline__ void mma16816(float* c, uint32_t a0, uint32_t a1,
                                         uint32_t a2, uint32_t a3,
                                         uint32_t b0, uint32_t b1) {
    asm volatile(
        "mma.sync.aligned.m16n8k16.row.col.f32.f16.f16.f32 "
        "{%0,%1,%2,%3}, {%4,%5,%6,%7}, {%8,%9}, {%0,%1,%2,%3};"
        : "+f"(c[0]), "+f"(c[1]), "+f"(c[2]), "+f"(c[3])
        : "r"(a0), "r"(a1), "r"(a2), "r"(a3), "r"(b0), "r"(b1));
}

__device__ __forceinline__ uint32_t sw_off(int row, int kbyte) {
    uint32_t off = (uint32_t)row * 128u + (uint32_t)kbyte;
    return off ^ ((off >> 3) & 0x70u);
}
__device__ __forceinline__ uint32_t pack_h(float a, float b) {
    __half2 h = __float22half2_rn(make_float2(a, b));
    return *(uint32_t*)&h;
}

// ---------------------------------------------------------------------------
// fp16 warp-MMA GEMM: C[m,n] = alpha * sum_k A[m,k]*B[n,k]
// Pure fp16 operands, fp32 accumulate.
// 128x128 CTA tile, 128 threads / 4 warps (2x2 grid, 64x64 warp tiles),
// K in 64-chunks, 3-stage cp.async pipeline (32KB/stage), 2 CTAs per SM.
// A batch index = z & amask; B/C batch index = z.
// OUTMODE 0: fp32 C.  OUTMODE 1: fp16 C (alpha applied).
// ---------------------------------------------------------------------------
#define STAGE_BYTES 32768
#define B_SM_OFF 16384
#define GEMM_SMEM (3 * STAGE_BYTES)
#define GTHREADS 128

__device__ __forceinline__ void stage_load(uint32_t sdst, const f16* __restrict__ A,
                                           const f16* __restrict__ B,
                                           int K, int k0, int t) {
#pragma unroll
    for (int i = 0; i < 8; i++) {         // A: 128 rows x 8 chunks
        int idx = t + i * GTHREADS;       // 0..1023
        int row = idx >> 3, ch = idx & 7;
        cp16(sdst + sw_off(row, ch * 16), A + (size_t)row * K + k0 + ch * 8);
    }
#pragma unroll
    for (int i = 0; i < 8; i++) {         // B: 128 rows x 8 chunks
        int idx = t + i * GTHREADS;
        int row = idx >> 3, ch = idx & 7;
        cp16(sdst + B_SM_OFF + sw_off(row, ch * 16), B + (size_t)row * K + k0 + ch * 8);
    }
}

template<int OUTMODE>
__global__ void __launch_bounds__(GTHREADS, 2)
mma_gemm(const f16* __restrict__ A, const f16* __restrict__ B,
         float* __restrict__ C, f16* __restrict__ Ch,
         int K, int ldc, long sA, long sB, long sC, float alpha, int amask)
{
    extern __shared__ __align__(1024) char smem[];
    const uint32_t sb = smem_u32(smem);
    const int t = threadIdx.x, lane = t & 31, wid = t >> 5;
    const int wm = wid & 1, wn = wid >> 1;          // 2x2 warp grid, 64x64 tiles
    const int m0 = blockIdx.y * 128, n0 = blockIdx.x * 128, z = blockIdx.z;
    const int kiters = K >> 6;

    A += (size_t)(z & amask) * sA + (size_t)m0 * K;
    B += (size_t)z * sB + (size_t)n0 * K;

    float acc[4][8][4];
#pragma unroll
    for (int i = 0; i < 4; i++)
#pragma unroll
        for (int j = 0; j < 8; j++)
#pragma unroll
            for (int q = 0; q < 4; q++) acc[i][j][q] = 0.f;

    // ldmatrix lane-address components
    const int a_m_add = (lane & 7) + ((lane >> 3) & 1) * 8;
    const int a_k_add = ((lane >> 4) & 1) * 8;
    // B x4: matrices (0,1) = n-tile +0 @ k 0/8; matrices (2,3) = n-tile +8 @ k 0/8
    const int b_n_add = (lane & 7) + ((lane >> 4) << 3);
    const int b_k_add = ((lane >> 3) & 1) * 8;

    stage_load(sb, A, B, K, 0, t);
    CP_COMMIT();
    if (kiters > 1) {
        stage_load(sb + STAGE_BYTES, A, B, K, 64, t);
        CP_COMMIT();
    }

    uint32_t cur = 0;  // rotating stage index
    for (int it = 0; it < kiters; it++) {
        if (it + 1 < kiters) { CP_WAIT1(); } else { CP_WAIT0(); }
        __syncthreads();
        if (it + 2 < kiters) {
            uint32_t nxt = cur + 2; if (nxt >= 3) nxt -= 3;
            stage_load(sb + nxt * STAGE_BYTES, A, B, K, (it + 2) << 6, t);
            CP_COMMIT();
        }
        const uint32_t st = sb + cur * STAGE_BYTES;

#pragma unroll
        for (int ks = 0; ks < 4; ks++) {
            const int kb = ks * 16;
            uint32_t ah[4][4];
#pragma unroll
            for (int tm = 0; tm < 4; tm++) {
                int m = wm * 64 + tm * 16 + a_m_add;
                uint32_t so = sw_off(m, (kb + a_k_add) * 2);
                ldmat_x4(ah[tm][0], ah[tm][1], ah[tm][2], ah[tm][3], st + so);
            }
            uint32_t bh[8][2];
#pragma unroll
            for (int tn2 = 0; tn2 < 4; tn2++) {
                int n = wn * 64 + tn2 * 16 + b_n_add;
                uint32_t so = sw_off(n, (kb + b_k_add) * 2);
                ldmat_x4(bh[tn2 * 2][0], bh[tn2 * 2][1],
                         bh[tn2 * 2 + 1][0], bh[tn2 * 2 + 1][1], st + B_SM_OFF + so);
            }
#pragma unroll
            for (int tm = 0; tm < 4; tm++)
#pragma unroll
                for (int tn = 0; tn < 8; tn++)
                    mma16816(acc[tm][tn], ah[tm][0], ah[tm][1], ah[tm][2], ah[tm][3],
                             bh[tn][0], bh[tn][1]);
        }
        cur = cur + 1; if (cur >= 3) cur -= 3;
    }

    // Epilogue
    const int gid = lane >> 2, tig = lane & 3;
#pragma unroll
    for (int tm = 0; tm < 4; tm++) {
        const int r0 = m0 + wm * 64 + tm * 16 + gid;
#pragma unroll
        for (int tn = 0; tn < 8; tn++) {
            const int cN = n0 + wn * 64 + tn * 8 + tig * 2;
            float* a = acc[tm][tn];
            if (OUTMODE == 0) {
                *(float2*)(C + (size_t)z * sC + (size_t)r0 * ldc + cN) =
                    make_float2(a[0] * alpha, a[1] * alpha);
                *(float2*)(C + (size_t)z * sC + (size_t)(r0 + 8) * ldc + cN) =
                    make_float2(a[2] * alpha, a[3] * alpha);
            } else {
                *(uint32_t*)(Ch + (size_t)z * sC + (size_t)r0 * ldc + cN) =
                    pack_h(a[0] * alpha, a[1] * alpha);
                *(uint32_t*)(Ch + (size_t)z * sC + (size_t)(r0 + 8) * ldc + cN) =
                    pack_h(a[2] * alpha, a[3] * alpha);
            }
        }
    }
}

// ---------------------------------------------------------------------------
// Prep kernels
// ---------------------------------------------------------------------------
// x [L,B,D] -> q fp16 [B,L,D]
__global__ void convert_q(const float* __restrict__ in, f16* __restrict__ q)
{
    const int l = blockIdx.x, b = blockIdx.y, t = threadIdx.x;
    const float* s = in + (size_t)l * (BB * DD) + (size_t)b * DD;
    const size_t o = ((size_t)b * LQ + l) * DD;
#pragma unroll
    for (int j = 0; j < 3; j++)
        q[o + t + j * 256] = __float2half(s[t + j * 256]);
}

// W_a/W_v -> fp16
__global__ void convert_w(const float* __restrict__ wa, const float* __restrict__ wv,
                          f16* __restrict__ w)
{
    const int br = blockIdx.y;
    const int i = blockIdx.x * 256 + threadIdx.x;
    w[br * DD * DD + i] = __float2half((br ? wv : wa)[i]);
}

// x_a/x_v [L,B,D] -> kv fp16 [z][L][D] AND kvT fp16 [z][D][L], z = br*8+b
__global__ void prep_kv(const float* __restrict__ xa, const float* __restrict__ xv,
                        f16* __restrict__ kv, f16* __restrict__ kT)
{
    __shared__ uint16_t th[32][33];
    const int z = blockIdx.z, b = z & 7;
    const float* src = (z >> 3) ? xv : xa;
    const int d0 = blockIdx.x * 32, l0 = blockIdx.y * 32;
    const int tx = threadIdx.x, ty = threadIdx.y;
#pragma unroll
    for (int r = 0; r < 4; r++) {
        int l = l0 + ty + r * 8;
        float v = src[(size_t)l * (BB * DD) + (size_t)b * DD + d0 + tx];
        uint16_t h = __half_as_ushort(__float2half(v));
        kv[((size_t)z * LQ + l) * DD + d0 + tx] = __ushort_as_half(h);
        th[ty + r * 8][tx] = h;
    }
    __syncthreads();
#pragma unroll
    for (int r = 0; r < 4; r++) {
        int d = d0 + ty + r * 8;
        kT[((size_t)z * DD + d) * LQ + l0 + tx] = __ushort_as_half(th[tx][ty + r * 8]);
    }
}

// ---------------------------------------------------------------------------
// In-place softmax over 2048-wide fp16 rows. grid = ZB*LQ, block = 256.
// ---------------------------------------------------------------------------
__global__ void softmax_f16ip(f16* __restrict__ S)
{
    __shared__ float red[8];
    f16* row = S + (size_t)blockIdx.x * 2048;
    const int t = threadIdx.x;

    uint4 raw = ((const uint4*)row)[t];
    float v[8];
    {
        uint32_t w[4] = {raw.x, raw.y, raw.z, raw.w};
#pragma unroll
        for (int i = 0; i < 4; i++) {
            __half2 hh = *(__half2*)&w[i];
            float2 f = __half22float2(hh);
            v[2 * i] = f.x; v[2 * i + 1] = f.y;
        }
    }

    float m = v[0];
#pragma unroll
    for (int i = 1; i < 8; i++) m = fmaxf(m, v[i]);
#pragma unroll
    for (int o = 16; o; o >>= 1) m = fmaxf(m, __shfl_xor_sync(~0u, m, o));
    if ((t & 31) == 0) red[t >> 5] = m;
    __syncthreads();
    float mx = red[0];
#pragma unroll
    for (int w = 1; w < 8; w++) mx = fmaxf(mx, red[w]);
    __syncthreads();

    float s = 0.f;
#pragma unroll
    for (int i = 0; i < 8; i++) { v[i] = __expf(v[i] - mx); s += v[i]; }
#pragma unroll
    for (int o = 16; o; o >>= 1) s += __shfl_xor_sync(~0u, s, o);
    if ((t & 31) == 0) red[t >> 5] = s;
    __syncthreads();
    float sm = 0.f;
#pragma unroll
    for (int w = 0; w < 8; w++) sm += red[w];
    const float inv = 1.f / sm;

    uint4 outw;
    outw.x = pack_h(v[0] * inv, v[1] * inv);
    outw.y = pack_h(v[2] * inv, v[3] * inv);
    outw.z = pack_h(v[4] * inv, v[5] * inv);
    outw.w = pack_h(v[6] * inv, v[7] * inv);
    ((uint4*)row)[t] = outw;
}

// ---------------------------------------------------------------------------
// BatchNorm stats (two-stage, deterministic; grid.y = branch) — fp16 y input
// ---------------------------------------------------------------------------
__global__ void bn_partial(const f16* __restrict__ yAll, float* __restrict__ partAll)
{
    const int br = blockIdx.y, t = threadIdx.x;
    const f16* base = yAll + (size_t)br * MROWS * DD + (size_t)blockIdx.x * 128 * DD;
    float* part = partAll + (size_t)br * 2 * 128 * DD;
    float s[3] = {0.f, 0.f, 0.f}, q[3] = {0.f, 0.f, 0.f};
    for (int r = 0; r < 128; r++) {
        const f16* row = base + (size_t)r * DD;
#pragma unroll
        for (int j = 0; j < 3; j++) {
            float v = __half2float(row[t + j * 256]);
            s[j] += v; q[j] += v * v;
        }
    }
#pragma unroll
    for (int j = 0; j < 3; j++) {
        part[blockIdx.x * DD + t + j * 256] = s[j];
        part[128 * DD + blockIdx.x * DD + t + j * 256] = q[j];
    }
}

__global__ void bn_finalize(const float* __restrict__ partAll,
                            const float* __restrict__ ga, const float* __restrict__ ba,
                            const float* __restrict__ gv, const float* __restrict__ bv,
                            float* __restrict__ statsAll)
{
    const int br = blockIdx.y;
    const int c = blockIdx.x * 256 + threadIdx.x;
    const float* part = partAll + (size_t)br * 2 * 128 * DD;
    const float* gamma = br ? gv : ga;
    const float* beta  = br ? bv : ba;
    float* statsOut = statsAll + br * 2 * DD;
    float s = 0.f, q = 0.f;
    for (int k = 0; k < 128; k++) {
        s += part[k * DD + c];
        q += part[128 * DD + k * DD + c];
    }
    const float mean = s * (1.f / (float)MROWS);
    const float var  = q * (1.f / (float)MROWS) - mean * mean;
    const float scale = gamma[c] * rsqrtf(var + 1e-5f);
    statsOut[c]      = scale;
    statsOut[DD + c] = beta[c] - mean * scale;
}

// ---------------------------------------------------------------------------
// Combine: BN-apply + PReLU + residual + LayerNorm. grid = MROWS. fp16 y input
// ---------------------------------------------------------------------------
__global__ void combine_ln(const float* __restrict__ x,
                           const f16* __restrict__ yAll,
                           const float* __restrict__ stats,
                           const float* __restrict__ pa,
                           const float* __restrict__ pv,
                           const float* __restrict__ lng,
                           const float* __restrict__ lnb,
                           float* __restrict__ out)
{
    __shared__ float rs[8], rq[8];
    const int pos = blockIdx.x;
    const int b = pos >> 11, l = pos & 2047;
    const size_t yoff = (size_t)pos * DD;
    const size_t xoff = (size_t)l * (BB * DD) + (size_t)b * DD;
    const int t = threadIdx.x;
    const float aa = pa[0], av = pv[0];
    const f16* ya = yAll;
    const f16* yv = yAll + (size_t)MROWS * DD;

    float vv[3];
    float s = 0.f, q = 0.f;
#pragma unroll
    for (int j = 0; j < 3; j++) {
        const int d = t + j * 256;
        float va = __half2float(ya[yoff + d]) * stats[d] + stats[DD + d];
        va = va > 0.f ? va : aa * va;
        float vb = __half2float(yv[yoff + d]) * stats[2 * DD + d] + stats[3 * DD + d];
        vb = vb > 0.f ? vb : av * vb;
        float val = x[xoff + d] + va + vb;
        vv[j] = val; s += val; q += val * val;
    }
#pragma unroll
    for (int o = 16; o; o >>= 1) {
        s += __shfl_xor_sync(~0u, s, o);
        q += __shfl_xor_sync(~0u, q, o);
    }
    if ((t & 31) == 0) { rs[t >> 5] = s; rq[t >> 5] = q; }
    __syncthreads();
    s = 0.f; q = 0.f;
#pragma unroll
    for (int w = 0; w < 8; w++) { s += rs[w]; q += rq[w]; }
    const float mean = s * (1.f / (float)DD);
    const float var  = q * (1.f / (float)DD) - mean * mean;
    const float rstd = rsqrtf(var + 1e-5f);
#pragma unroll
    for (int j = 0; j < 3; j++) {
        const int d = t + j * 256;
        out[xoff + d] = (vv[j] - mean) * rstd * lng[d] + lnb[d];
    }
}

// ---------------------------------------------------------------------------
// Host orchestration (graph-capturable)
// ---------------------------------------------------------------------------
extern "C" void kernel_launch(void* const* d_in, const int* in_sizes, int n_in,
                              void* d_out, int out_size)
{
    const float* x_a    = (const float*)d_in[0];
    const float* x_v    = (const float*)d_in[1];
    const float* x      = (const float*)d_in[2];
    const float* W_a    = (const float*)d_in[3];
    const float* bn_a_g = (const float*)d_in[5];
    const float* bn_a_b = (const float*)d_in[6];
    const float* pre_a  = (const float*)d_in[7];
    const float* W_v    = (const float*)d_in[8];
    const float* bn_v_g = (const float*)d_in[10];
    const float* bn_v_b = (const float*)d_in[11];
    const float* pre_v  = (const float*)d_in[12];
    const float* ln_g   = (const float*)d_in[13];
    const float* ln_b   = (const float*)d_in[14];
    float* out = (float*)d_out;

    float *part, *stats;
    f16 *S, *q, *kv, *kT, *c, *W, *y;
    cudaGetSymbolAddress((void**)&S,    g_S);
    cudaGetSymbolAddress((void**)&q,    g_q);
    cudaGetSymbolAddress((void**)&kv,   g_kv);
    cudaGetSymbolAddress((void**)&kT,   g_kT);
    cudaGetSymbolAddress((void**)&c,    g_c);
    cudaGetSymbolAddress((void**)&W,    g_W);
    cudaGetSymbolAddress((void**)&y,    g_y);
    cudaGetSymbolAddress((void**)&part, g_part);
    cudaGetSymbolAddress((void**)&stats, g_stats);

    cudaFuncSetAttribute(mma_gemm<0>, cudaFuncAttributeMaxDynamicSharedMemorySize, GEMM_SMEM);
    cudaFuncSetAttribute(mma_gemm<1>, cudaFuncAttributeMaxDynamicSharedMemorySize, GEMM_SMEM);

    // Prep: q, W, kv/kvT (both branches)
    convert_q<<<dim3(LQ, BB), 256>>>(x, q);
    convert_w<<<dim3((DD * DD) / 256, 2), 256>>>(W_a, W_v, W);
    prep_kv<<<dim3(DD / 32, LQ / 32, ZB), dim3(32, 8)>>>(x_a, x_v, kv, kT);

    // GEMM1: S[z,i,j] = scale * q[z&7,i,:].kv[z,j,:]  -> fp16 logits (scale folded)
    mma_gemm<1><<<dim3(16, 16, ZB), GTHREADS, GEMM_SMEM>>>(
        q, kv, nullptr, S,
        DD, LQ, (long)LQ * DD, (long)LQ * DD, (long)LQ * LQ, QKSCALE, 7);

    // In-place softmax: fp16 logits -> fp16 probs
    softmax_f16ip<<<ZB * LQ, 256>>>(S);

    // GEMM2: ctx[z,i,d] = P[z,i,:].kvT[z,d,:]  -> fp16 ctx
    mma_gemm<1><<<dim3(6, 16, ZB), GTHREADS, GEMM_SMEM>>>(
        S, kT, nullptr, c,
        LQ, DD, (long)LQ * LQ, (long)DD * LQ, (long)LQ * DD, 1.f, 0xFF);

    // GEMM3: y[br,r,e] = ctx[br,r,:].W[br,e,:]  -> fp16 y (bias cancels in BN)
    mma_gemm<1><<<dim3(6, 128, 2), GTHREADS, GEMM_SMEM>>>(
        c, W, nullptr, y,
        DD, DD, (long)MROWS * DD, (long)DD * DD, (long)MROWS * DD, 1.f, 0xFF);

    bn_partial<<<dim3(128, 2), 256>>>(y, part);
    bn_finalize<<<dim3(3, 2), 256>>>(part, bn_a_g, bn_a_b, bn_v_g, bn_v_b, stats);

    combine_ln<<<MROWS, 256>>>(x, y, stats, pre_a, pre_v, ln_g, ln_b, out);
}

// round 14
// speedup vs baseline: 2.7124x; 1.0413x over previous
#include <cuda_runtime.h>
#include <cuda_fp16.h>
#include <cstdint>

#define LQ 2048
#define BB 8
#define DD 768
#define MROWS (BB * LQ)
#define ZB (2 * BB)                 // branch*8 + batch
#define QKSCALE 0.0360843918243516f

using f16 = __half;

// ---------------------------------------------------------------------------
// Scratch (device globals; allocation-free per harness rules)
// ---------------------------------------------------------------------------
__device__ __align__(16) f16   g_S[(size_t)ZB * LQ * LQ];     // 128MB exp-logits (unnormalized)
__device__ __align__(16) f16   g_q[(size_t)MROWS * DD];
__device__ __align__(16) f16   g_kv[(size_t)2 * MROWS * DD];
__device__ __align__(16) f16   g_kT[(size_t)2 * MROWS * DD];
__device__ __align__(16) f16   g_c[(size_t)2 * MROWS * DD];
__device__ __align__(16) f16   g_W[2 * DD * DD];
__device__ __align__(16) f16   g_y[(size_t)2 * MROWS * DD];   // conv out fp16, both branches
__device__ float g_rspart[(size_t)ZB * LQ * 16];              // softmax row partial sums
__device__ float g_rsinv[(size_t)ZB * LQ];                    // 1/rowsum
__device__ float g_part[2 * 2 * 128 * DD];
__device__ float g_stats[2 * 2 * DD];

// ---------------------------------------------------------------------------
// Helpers (baseline PTX only: ldmatrix / mma.sync / cp.async)
// ---------------------------------------------------------------------------
__device__ __forceinline__ uint32_t smem_u32(const void* p) {
    uint32_t a;
    asm("{ .reg .u64 t; cvta.to.shared.u64 t, %1; cvt.u32.u64 %0, t; }" : "=r"(a) : "l"(p));
    return a;
}
__device__ __forceinline__ void cp16(uint32_t saddr, const void* gaddr) {
    asm volatile("cp.async.cg.shared.global [%0], [%1], 16;" :: "r"(saddr), "l"(gaddr));
}
#define CP_COMMIT() asm volatile("cp.async.commit_group;" ::: "memory")
#define CP_WAIT0()  asm volatile("cp.async.wait_group 0;" ::: "memory")
#define CP_WAIT1()  asm volatile("cp.async.wait_group 1;" ::: "memory")

__device__ __forceinline__ void ldmat_x4(uint32_t& r0, uint32_t& r1, uint32_t& r2,
                                         uint32_t& r3, uint32_t addr) {
    asm volatile("ldmatrix.sync.aligned.m8n8.x4.shared.b16 {%0,%1,%2,%3}, [%4];"
                 : "=r"(r0), "=r"(r1), "=r"(r2), "=r"(r3) : "r"(addr));
}
__device__ __forceinline__ void mma16816(float* c, uint32_t a0, uint32_t a1,
                                         uint32_t a2, uint32_t a3,
                                         uint32_t b0, uint32_t b1) {
    asm volatile(
        "mma.sync.aligned.m16n8k16.row.col.f32.f16.f16.f32 "
        "{%0,%1,%2,%3}, {%4,%5,%6,%7}, {%8,%9}, {%0,%1,%2,%3};"
        : "+f"(c[0]), "+f"(c[1]), "+f"(c[2]), "+f"(c[3])
        : "r"(a0), "r"(a1), "r"(a2), "r"(a3), "r"(b0), "r"(b1));
}

__device__ __forceinline__ uint32_t sw_off(int row, int kbyte) {
    uint32_t off = (uint32_t)row * 128u + (uint32_t)kbyte;
    return off ^ ((off >> 3) & 0x70u);
}
__device__ __forceinline__ uint32_t pack_h(float a, float b) {
    __half2 h = __float22half2_rn(make_float2(a, b));
    return *(uint32_t*)&h;
}

// ---------------------------------------------------------------------------
// fp16 warp-MMA GEMM: C[m,n] = alpha * sum_k A[m,k]*B[n,k]
// 128x128 CTA tile, 128 threads / 4 warps (2x2 grid, 64x64 warp tiles),
// K in 64-chunks, 3-stage cp.async pipeline (32KB/stage), 2 CTAs per SM.
// A batch index = z & amask; B/C batch index = z.
// OUTMODE 1: fp16 C (alpha applied; optional per-row scale from rowscale[]).
// OUTMODE 2: fp16 exp(alpha*acc) into Ch + per-row partial sums to rsum_part.
// ---------------------------------------------------------------------------
#define STAGE_BYTES 32768
#define B_SM_OFF 16384
#define GEMM_SMEM (3 * STAGE_BYTES)
#define GTHREADS 128

__device__ __forceinline__ void stage_load(uint32_t sdst, const f16* __restrict__ A,
                                           const f16* __restrict__ B,
                                           int K, int k0, int t) {
#pragma unroll
    for (int i = 0; i < 8; i++) {         // A: 128 rows x 8 chunks
        int idx = t + i * GTHREADS;       // 0..1023
        int row = idx >> 3, ch = idx & 7;
        cp16(sdst + sw_off(row, ch * 16), A + (size_t)row * K + k0 + ch * 8);
    }
#pragma unroll
    for (int i = 0; i < 8; i++) {         // B: 128 rows x 8 chunks
        int idx = t + i * GTHREADS;
        int row = idx >> 3, ch = idx & 7;
        cp16(sdst + B_SM_OFF + sw_off(row, ch * 16), B + (size_t)row * K + k0 + ch * 8);
    }
}

template<int OUTMODE>
__global__ void __launch_bounds__(GTHREADS, 2)
mma_gemm(const f16* __restrict__ A, const f16* __restrict__ B,
         f16* __restrict__ Ch, const float* __restrict__ rowscale,
         float* __restrict__ rsum_part,
         int K, int ldc, long sA, long sB, long sC, float alpha, int amask)
{
    extern __shared__ __align__(1024) char smem[];
    const uint32_t sb = smem_u32(smem);
    const int t = threadIdx.x, lane = t & 31, wid = t >> 5;
    const int wm = wid & 1, wn = wid >> 1;          // 2x2 warp grid, 64x64 tiles
    const int m0 = blockIdx.y * 128, n0 = blockIdx.x * 128, z = blockIdx.z;
    const int kiters = K >> 6;

    A += (size_t)(z & amask) * sA + (size_t)m0 * K;
    B += (size_t)z * sB + (size_t)n0 * K;

    float acc[4][8][4];
#pragma unroll
    for (int i = 0; i < 4; i++)
#pragma unroll
        for (int j = 0; j < 8; j++)
#pragma unroll
            for (int q = 0; q < 4; q++) acc[i][j][q] = 0.f;

    // ldmatrix lane-address components
    const int a_m_add = (lane & 7) + ((lane >> 3) & 1) * 8;
    const int a_k_add = ((lane >> 4) & 1) * 8;
    const int b_n_add = (lane & 7) + ((lane >> 4) << 3);
    const int b_k_add = ((lane >> 3) & 1) * 8;

    stage_load(sb, A, B, K, 0, t);
    CP_COMMIT();
    if (kiters > 1) {
        stage_load(sb + STAGE_BYTES, A, B, K, 64, t);
        CP_COMMIT();
    }

    uint32_t cur = 0;
    for (int it = 0; it < kiters; it++) {
        if (it + 1 < kiters) { CP_WAIT1(); } else { CP_WAIT0(); }
        __syncthreads();
        if (it + 2 < kiters) {
            uint32_t nxt = cur + 2; if (nxt >= 3) nxt -= 3;
            stage_load(sb + nxt * STAGE_BYTES, A, B, K, (it + 2) << 6, t);
            CP_COMMIT();
        }
        const uint32_t st = sb + cur * STAGE_BYTES;

#pragma unroll
        for (int ks = 0; ks < 4; ks++) {
            const int kb = ks * 16;
            uint32_t ah[4][4];
#pragma unroll
            for (int tm = 0; tm < 4; tm++) {
                int m = wm * 64 + tm * 16 + a_m_add;
                uint32_t so = sw_off(m, (kb + a_k_add) * 2);
                ldmat_x4(ah[tm][0], ah[tm][1], ah[tm][2], ah[tm][3], st + so);
            }
            uint32_t bh[8][2];
#pragma unroll
            for (int tn2 = 0; tn2 < 4; tn2++) {
                int n = wn * 64 + tn2 * 16 + b_n_add;
                uint32_t so = sw_off(n, (kb + b_k_add) * 2);
                ldmat_x4(bh[tn2 * 2][0], bh[tn2 * 2][1],
                         bh[tn2 * 2 + 1][0], bh[tn2 * 2 + 1][1], st + B_SM_OFF + so);
            }
#pragma unroll
            for (int tm = 0; tm < 4; tm++)
#pragma unroll
                for (int tn = 0; tn < 8; tn++)
                    mma16816(acc[tm][tn], ah[tm][0], ah[tm][1], ah[tm][2], ah[tm][3],
                             bh[tn][0], bh[tn][1]);
        }
        cur = cur + 1; if (cur >= 3) cur -= 3;
    }

    // Epilogue
    const int gid = lane >> 2, tig = lane & 3;
    if (OUTMODE == 1) {
#pragma unroll
        for (int tm = 0; tm < 4; tm++) {
            const int r0 = m0 + wm * 64 + tm * 16 + gid;
            float rs0 = 1.f, rs1 = 1.f;
            if (rowscale) {
                rs0 = rowscale[(size_t)z * LQ + r0];
                rs1 = rowscale[(size_t)z * LQ + r0 + 8];
            }
#pragma unroll
            for (int tn = 0; tn < 8; tn++) {
                const int cN = n0 + wn * 64 + tn * 8 + tig * 2;
                float* a = acc[tm][tn];
                *(uint32_t*)(Ch + (size_t)z * sC + (size_t)r0 * ldc + cN) =
                    pack_h(a[0] * alpha * rs0, a[1] * alpha * rs0);
                *(uint32_t*)(Ch + (size_t)z * sC + (size_t)(r0 + 8) * ldc + cN) =
                    pack_h(a[2] * alpha * rs1, a[3] * alpha * rs1);
            }
        }
    } else {
        // OUTMODE 2: exp epilogue + deterministic per-row partial sums
        float* rsum = (float*)smem;  // [2][128] floats (reuses stage smem)
        __syncthreads();             // all MMAs/loads done; safe to reuse
#pragma unroll
        for (int tm = 0; tm < 4; tm++) {
            const int rr = wm * 64 + tm * 16 + gid;     // row within CTA
            const int r0 = m0 + rr;
            float sum0 = 0.f, sum1 = 0.f;
#pragma unroll
            for (int tn = 0; tn < 8; tn++) {
                const int cN = n0 + wn * 64 + tn * 8 + tig * 2;
                float* a = acc[tm][tn];
                float e0 = __expf(a[0] * alpha), e1 = __expf(a[1] * alpha);
                float e2 = __expf(a[2] * alpha), e3 = __expf(a[3] * alpha);
                *(uint32_t*)(Ch + (size_t)z * sC + (size_t)r0 * ldc + cN) = pack_h(e0, e1);
                *(uint32_t*)(Ch + (size_t)z * sC + (size_t)(r0 + 8) * ldc + cN) = pack_h(e2, e3);
                sum0 += e0 + e1;
                sum1 += e2 + e3;
            }
            sum0 += __shfl_xor_sync(~0u, sum0, 1);
            sum0 += __shfl_xor_sync(~0u, sum0, 2);
            sum1 += __shfl_xor_sync(~0u, sum1, 1);
            sum1 += __shfl_xor_sync(~0u, sum1, 2);
            if (tig == 0) {
                rsum[wn * 128 + rr] = sum0;
                rsum[wn * 128 + rr + 8] = sum1;
            }
        }
        __syncthreads();
        if (t < 128) {
            float v = rsum[t] + rsum[128 + t];
            rsum_part[((size_t)z * LQ + m0 + t) * 16 + blockIdx.x] = v;
        }
    }
}

// Finalize: inv[z][i] = 1 / sum of 16 partials. grid = ZB*LQ/256.
__global__ void rowsum_fin(const float* __restrict__ part, float* __restrict__ inv)
{
    const size_t i = (size_t)blockIdx.x * 256 + threadIdx.x;
    const float* p = part + i * 16;
    float s = 0.f;
#pragma unroll
    for (int k = 0; k < 16; k++) s += p[k];
    inv[i] = 1.f / s;
}

// ---------------------------------------------------------------------------
// Prep kernels
// ---------------------------------------------------------------------------
__global__ void convert_q(const float* __restrict__ in, f16* __restrict__ q)
{
    const int l = blockIdx.x, b = blockIdx.y, t = threadIdx.x;
    const float* s = in + (size_t)l * (BB * DD) + (size_t)b * DD;
    const size_t o = ((size_t)b * LQ + l) * DD;
#pragma unroll
    for (int j = 0; j < 3; j++)
        q[o + t + j * 256] = __float2half(s[t + j * 256]);
}

__global__ void convert_w(const float* __restrict__ wa, const float* __restrict__ wv,
                          f16* __restrict__ w)
{
    const int br = blockIdx.y;
    const int i = blockIdx.x * 256 + threadIdx.x;
    w[br * DD * DD + i] = __float2half((br ? wv : wa)[i]);
}

__global__ void prep_kv(const float* __restrict__ xa, const float* __restrict__ xv,
                        f16* __restrict__ kv, f16* __restrict__ kT)
{
    __shared__ uint16_t th[32][33];
    const int z = blockIdx.z, b = z & 7;
    const float* src = (z >> 3) ? xv : xa;
    const int d0 = blockIdx.x * 32, l0 = blockIdx.y * 32;
    const int tx = threadIdx.x, ty = threadIdx.y;
#pragma unroll
    for (int r = 0; r < 4; r++) {
        int l = l0 + ty + r * 8;
        float v = src[(size_t)l * (BB * DD) + (size_t)b * DD + d0 + tx];
        uint16_t h = __half_as_ushort(__float2half(v));
        kv[((size_t)z * LQ + l) * DD + d0 + tx] = __ushort_as_half(h);
        th[ty + r * 8][tx] = h;
    }
    __syncthreads();
#pragma unroll
    for (int r = 0; r < 4; r++) {
        int d = d0 + ty + r * 8;
        kT[((size_t)z * DD + d) * LQ + l0 + tx] = __ushort_as_half(th[tx][ty + r * 8]);
    }
}

// ---------------------------------------------------------------------------
// BatchNorm stats (two-stage, deterministic; grid.y = branch) — fp16 y input
// ---------------------------------------------------------------------------
__global__ void bn_partial(const f16* __restrict__ yAll, float* __restrict__ partAll)
{
    const int br = blockIdx.y, t = threadIdx.x;
    const f16* base = yAll + (size_t)br * MROWS * DD + (size_t)blockIdx.x * 128 * DD;
    float* part = partAll + (size_t)br * 2 * 128 * DD;
    float s[3] = {0.f, 0.f, 0.f}, q[3] = {0.f, 0.f, 0.f};
    for (int r = 0; r < 128; r++) {
        const f16* row = base + (size_t)r * DD;
#pragma unroll
        for (int j = 0; j < 3; j++) {
            float v = __half2float(row[t + j * 256]);
            s[j] += v; q[j] += v * v;
        }
    }
#pragma unroll
    for (int j = 0; j < 3; j++) {
        part[blockIdx.x * DD + t + j * 256] = s[j];
        part[128 * DD + blockIdx.x * DD + t + j * 256] = q[j];
    }
}

__global__ void bn_finalize(const float* __restrict__ partAll,
                            const float* __restrict__ ga, const float* __restrict__ ba,
                            const float* __restrict__ gv, const float* __restrict__ bv,
                            float* __restrict__ statsAll)
{
    const int br = blockIdx.y;
    const int c = blockIdx.x * 256 + threadIdx.x;
    const float* part = partAll + (size_t)br * 2 * 128 * DD;
    const float* gamma = br ? gv : ga;
    const float* beta  = br ? bv : ba;
    float* statsOut = statsAll + br * 2 * DD;
    float s = 0.f, q = 0.f;
    for (int k = 0; k < 128; k++) {
        s += part[k * DD + c];
        q += part[128 * DD + k * DD + c];
    }
    const float mean = s * (1.f / (float)MROWS);
    const float var  = q * (1.f / (float)MROWS) - mean * mean;
    const float scale = gamma[c] * rsqrtf(var + 1e-5f);
    statsOut[c]      = scale;
    statsOut[DD + c] = beta[c] - mean * scale;
}

// ---------------------------------------------------------------------------
// Combine: BN-apply + PReLU + residual + LayerNorm. grid = MROWS.
// ---------------------------------------------------------------------------
__global__ void combine_ln(const float* __restrict__ x,
                           const f16* __restrict__ yAll,
                           const float* __restrict__ stats,
                           const float* __restrict__ pa,
                           const float* __restrict__ pv,
                           const float* __restrict__ lng,
                           const float* __restrict__ lnb,
                           float* __restrict__ out)
{
    __shared__ float rs[8], rq[8];
    const int pos = blockIdx.x;
    const int b = pos >> 11, l = pos & 2047;
    const size_t yoff = (size_t)pos * DD;
    const size_t xoff = (size_t)l * (BB * DD) + (size_t)b * DD;
    const int t = threadIdx.x;
    const float aa = pa[0], av = pv[0];
    const f16* ya = yAll;
    const f16* yv = yAll + (size_t)MROWS * DD;

    float vv[3];
    float s = 0.f, q = 0.f;
#pragma unroll
    for (int j = 0; j < 3; j++) {
        const int d = t + j * 256;
        float va = __half2float(ya[yoff + d]) * stats[d] + stats[DD + d];
        va = va > 0.f ? va : aa * va;
        float vb = __half2float(yv[yoff + d]) * stats[2 * DD + d] + stats[3 * DD + d];
        vb = vb > 0.f ? vb : av * vb;
        float val = x[xoff + d] + va + vb;
        vv[j] = val; s += val; q += val * val;
    }
#pragma unroll
    for (int o = 16; o; o >>= 1) {
        s += __shfl_xor_sync(~0u, s, o);
        q += __shfl_xor_sync(~0u, q, o);
    }
    if ((t & 31) == 0) { rs[t >> 5] = s; rq[t >> 5] = q; }
    __syncthreads();
    s = 0.f; q = 0.f;
#pragma unroll
    for (int w = 0; w < 8; w++) { s += rs[w]; q += rq[w]; }
    const float mean = s * (1.f / (float)DD);
    const float var  = q * (1.f / (float)DD) - mean * mean;
    const float rstd = rsqrtf(var + 1e-5f);
#pragma unroll
    for (int j = 0; j < 3; j++) {
        const int d = t + j * 256;
        out[xoff + d] = (vv[j] - mean) * rstd * lng[d] + lnb[d];
    }
}

// ---------------------------------------------------------------------------
// Host orchestration (graph-capturable)
// ---------------------------------------------------------------------------
extern "C" void kernel_launch(void* const* d_in, const int* in_sizes, int n_in,
                              void* d_out, int out_size)
{
    const float* x_a    = (const float*)d_in[0];
    const float* x_v    = (const float*)d_in[1];
    const float* x      = (const float*)d_in[2];
    const float* W_a    = (const float*)d_in[3];
    const float* bn_a_g = (const float*)d_in[5];
    const float* bn_a_b = (const float*)d_in[6];
    const float* pre_a  = (const float*)d_in[7];
    const float* W_v    = (const float*)d_in[8];
    const float* bn_v_g = (const float*)d_in[10];
    const float* bn_v_b = (const float*)d_in[11];
    const float* pre_v  = (const float*)d_in[12];
    const float* ln_g   = (const float*)d_in[13];
    const float* ln_b   = (const float*)d_in[14];
    float* out = (float*)d_out;

    float *part, *stats, *rspart, *rsinv;
    f16 *S, *q, *kv, *kT, *c, *W, *y;
    cudaGetSymbolAddress((void**)&S,      g_S);
    cudaGetSymbolAddress((void**)&q,      g_q);
    cudaGetSymbolAddress((void**)&kv,     g_kv);
    cudaGetSymbolAddress((void**)&kT,     g_kT);
    cudaGetSymbolAddress((void**)&c,      g_c);
    cudaGetSymbolAddress((void**)&W,      g_W);
    cudaGetSymbolAddress((void**)&y,      g_y);
    cudaGetSymbolAddress((void**)&rspart, g_rspart);
    cudaGetSymbolAddress((void**)&rsinv,  g_rsinv);
    cudaGetSymbolAddress((void**)&part,   g_part);
    cudaGetSymbolAddress((void**)&stats,  g_stats);

    cudaFuncSetAttribute(mma_gemm<1>, cudaFuncAttributeMaxDynamicSharedMemorySize, GEMM_SMEM);
    cudaFuncSetAttribute(mma_gemm<2>, cudaFuncAttributeMaxDynamicSharedMemorySize, GEMM_SMEM);

    // Prep: q, W, kv/kvT (both branches)
    convert_q<<<dim3(LQ, BB), 256>>>(x, q);
    convert_w<<<dim3((DD * DD) / 256, 2), 256>>>(W_a, W_v, W);
    prep_kv<<<dim3(DD / 32, LQ / 32, ZB), dim3(32, 8)>>>(x_a, x_v, kv, kT);

    // GEMM1 + exp epilogue: S = exp(scale * q.kv), partial row sums
    mma_gemm<2><<<dim3(16, 16, ZB), GTHREADS, GEMM_SMEM>>>(
        q, kv, S, nullptr, rspart,
        DD, LQ, (long)LQ * DD, (long)LQ * DD, (long)LQ * LQ, QKSCALE, 7);

    rowsum_fin<<<(ZB * LQ) / 256, 256>>>(rspart, rsinv);

    // GEMM2: ctx[z,i,d] = invsum[z,i] * sum_j S[z,i,j]*kvT[z,d,j]
    mma_gemm<1><<<dim3(6, 16, ZB), GTHREADS, GEMM_SMEM>>>(
        S, kT, c, rsinv, nullptr,
        LQ, DD, (long)LQ * LQ, (long)DD * LQ, (long)LQ * DD, 1.f, 0xFF);

    // GEMM3: y[br,r,e] = ctx[br,r,:].W[br,e,:]  (bias cancels in BN)
    mma_gemm<1><<<dim3(6, 128, 2), GTHREADS, GEMM_SMEM>>>(
        c, W, y, nullptr, nullptr,
        DD, DD, (long)MROWS * DD, (long)DD * DD, (long)MROWS * DD, 1.f, 0xFF);

    bn_partial<<<dim3(128, 2), 256>>>(y, part);
    bn_finalize<<<dim3(3, 2), 256>>>(part, bn_a_g, bn_a_b, bn_v_g, bn_v_b, stats);

    combine_ln<<<MROWS, 256>>>(x, y, stats, pre_a, pre_v, ln_g, ln_b, out);
}